// round 1
// baseline (speedup 1.0000x reference)
#include <cuda_runtime.h>
#include <math.h>

#define B_  2
#define S_  2048
#define D_  1024
#define H_  16
#define DH_ 64

// Scratch (allocation-free): Q, K, V projections and attention output.
__device__ float g_Q[B_ * S_ * D_];
__device__ float g_K[B_ * S_ * D_];
__device__ float g_V[B_ * S_ * D_];
__device__ float g_A[B_ * S_ * D_];

// ---------------------------------------------------------------------------
// SGEMM: C[M,N] = A[M,K] @ W[N,K]^T + bias[N]
// 128x128 block tile, BK=8, 256 threads, 8x8 per thread.
// ---------------------------------------------------------------------------
__global__ __launch_bounds__(256) void sgemm_nt(
    const float* __restrict__ A, const float* __restrict__ W,
    const float* __restrict__ bias, float* __restrict__ C,
    int M, int N, int K)
{
    __shared__ float As[8][128];
    __shared__ float Bs[8][128];

    const int tid = threadIdx.x;
    const int bn = blockIdx.x, bm = blockIdx.y;

    const int lrow = tid >> 1;          // 0..127
    const int lk   = (tid & 1) * 4;     // 0 or 4

    const float* Ap = A + (size_t)(bm * 128 + lrow) * K + lk;
    const float* Wp = W + (size_t)(bn * 128 + lrow) * K + lk;

    const int tr = tid >> 4;            // 0..15  (row group)
    const int tc = tid & 15;            // 0..15  (col group)

    float acc[8][8];
#pragma unroll
    for (int i = 0; i < 8; i++)
#pragma unroll
        for (int j = 0; j < 8; j++) acc[i][j] = 0.f;

    for (int kt = 0; kt < K; kt += 8) {
        float4 av = *(const float4*)(Ap + kt);
        float4 wv = *(const float4*)(Wp + kt);
        As[lk + 0][lrow] = av.x; As[lk + 1][lrow] = av.y;
        As[lk + 2][lrow] = av.z; As[lk + 3][lrow] = av.w;
        Bs[lk + 0][lrow] = wv.x; Bs[lk + 1][lrow] = wv.y;
        Bs[lk + 2][lrow] = wv.z; Bs[lk + 3][lrow] = wv.w;
        __syncthreads();

#pragma unroll
        for (int k = 0; k < 8; k++) {
            float4 a0 = *(const float4*)&As[k][tr * 8];
            float4 a1 = *(const float4*)&As[k][tr * 8 + 4];
            float4 b0 = *(const float4*)&Bs[k][tc * 8];
            float4 b1 = *(const float4*)&Bs[k][tc * 8 + 4];
            float a[8] = {a0.x, a0.y, a0.z, a0.w, a1.x, a1.y, a1.z, a1.w};
            float b[8] = {b0.x, b0.y, b0.z, b0.w, b1.x, b1.y, b1.z, b1.w};
#pragma unroll
            for (int i = 0; i < 8; i++)
#pragma unroll
                for (int j = 0; j < 8; j++)
                    acc[i][j] += a[i] * b[j];
        }
        __syncthreads();
    }

    const int n0 = bn * 128 + tc * 8;
#pragma unroll
    for (int i = 0; i < 8; i++) {
        int m = bm * 128 + tr * 8 + i;
        float* Cp = C + (size_t)m * N + n0;
#pragma unroll
        for (int j = 0; j < 8; j++)
            Cp[j] = acc[i][j] + bias[n0 + j];
    }
}

// ---------------------------------------------------------------------------
// Flash attention (fp32, online softmax).
// Grid: (S/64, H, B). Block: 256 threads (16x16), each thread owns a 4x4
// subtile of the 64x64 score tile and a 4x4 subtile of the 64x64 O tile.
// ---------------------------------------------------------------------------
#define PAD 72

__global__ __launch_bounds__(256) void attn_kernel(
    const float* __restrict__ Q, const float* __restrict__ K,
    const float* __restrict__ V, float* __restrict__ O)
{
    extern __shared__ float sm[];
    float* Qs = sm;                  // 64 * PAD
    float* Ks = Qs + 64 * PAD;
    float* Vs = Ks + 64 * PAD;
    float* Ps = Vs + 64 * PAD;

    const int tid = threadIdx.x;
    const int tx = tid & 15;         // key-col / dh-col group
    const int ty = tid >> 4;         // query-row group
    const int q0 = blockIdx.x * 64;
    const int h  = blockIdx.y;
    const int b  = blockIdx.z;

    const size_t base = ((size_t)b * S_) * D_ + (size_t)h * DH_;
    const float* Qg = Q + base + (size_t)q0 * D_;

    // Load Q tile (64 rows x 64 cols), row stride D_ in global.
    for (int i = tid; i < 64 * 16; i += 256) {
        int r = i >> 4, c = (i & 15) * 4;
        float4 v = *(const float4*)(Qg + (size_t)r * D_ + c);
        float* q = &Qs[r * PAD + c];
        q[0] = v.x; q[1] = v.y; q[2] = v.z; q[3] = v.w;
    }

    float acc[4][4];
    float mi[4], li[4];
#pragma unroll
    for (int i = 0; i < 4; i++) {
        mi[i] = -1e30f; li[i] = 0.f;
#pragma unroll
        for (int j = 0; j < 4; j++) acc[i][j] = 0.f;
    }

    for (int kt = 0; kt < S_; kt += 64) {
        __syncthreads();   // previous PV done with Ks/Vs/Ps
        const float* Kg = K + base + (size_t)kt * D_;
        const float* Vg = V + base + (size_t)kt * D_;
        for (int i = tid; i < 64 * 16; i += 256) {
            int r = i >> 4, c = (i & 15) * 4;
            float4 kv = *(const float4*)(Kg + (size_t)r * D_ + c);
            float* kd = &Ks[r * PAD + c];
            kd[0] = kv.x; kd[1] = kv.y; kd[2] = kv.z; kd[3] = kv.w;
            float4 vv = *(const float4*)(Vg + (size_t)r * D_ + c);
            float* vd = &Vs[r * PAD + c];
            vd[0] = vv.x; vd[1] = vv.y; vd[2] = vv.z; vd[3] = vv.w;
        }
        __syncthreads();

        // Scores: s[i][j] = Q[ty*4+i] . K[tx*4+j]
        float s[4][4];
#pragma unroll
        for (int i = 0; i < 4; i++)
#pragma unroll
            for (int j = 0; j < 4; j++) s[i][j] = 0.f;

#pragma unroll
        for (int d = 0; d < 64; d += 4) {
            float4 qv[4], kv[4];
#pragma unroll
            for (int i = 0; i < 4; i++)
                qv[i] = *(const float4*)&Qs[(ty * 4 + i) * PAD + d];
#pragma unroll
            for (int j = 0; j < 4; j++)
                kv[j] = *(const float4*)&Ks[(tx * 4 + j) * PAD + d];
#pragma unroll
            for (int i = 0; i < 4; i++)
#pragma unroll
                for (int j = 0; j < 4; j++)
                    s[i][j] += qv[i].x * kv[j].x + qv[i].y * kv[j].y +
                               qv[i].z * kv[j].z + qv[i].w * kv[j].w;
        }

        const float scale = 0.125f;  // 1/sqrt(64)
#pragma unroll
        for (int i = 0; i < 4; i++) {
            float tm = -1e30f;
#pragma unroll
            for (int j = 0; j < 4; j++) {
                s[i][j] *= scale;
                tm = fmaxf(tm, s[i][j]);
            }
            // reduce max over the 16 threads of this query row
#pragma unroll
            for (int off = 8; off; off >>= 1)
                tm = fmaxf(tm, __shfl_xor_sync(0xffffffffu, tm, off));
            float mn   = fmaxf(mi[i], tm);
            float corr = __expf(mi[i] - mn);
            float rs = 0.f;
#pragma unroll
            for (int j = 0; j < 4; j++) {
                s[i][j] = __expf(s[i][j] - mn);
                rs += s[i][j];
            }
#pragma unroll
            for (int off = 8; off; off >>= 1)
                rs += __shfl_xor_sync(0xffffffffu, rs, off);
            li[i] = li[i] * corr + rs;
            mi[i] = mn;
#pragma unroll
            for (int j = 0; j < 4; j++) {
                acc[i][j] *= corr;
                Ps[(ty * 4 + i) * PAD + tx * 4 + j] = s[i][j];
            }
        }
        __syncthreads();

        // O += P @ V   (P: 64x64 in shared, V: 64x64 in shared)
#pragma unroll 8
        for (int k = 0; k < 64; k++) {
            float4 vv = *(const float4*)&Vs[k * PAD + tx * 4];
            float pv[4];
#pragma unroll
            for (int i = 0; i < 4; i++)
                pv[i] = Ps[(ty * 4 + i) * PAD + k];
#pragma unroll
            for (int i = 0; i < 4; i++) {
                acc[i][0] += pv[i] * vv.x;
                acc[i][1] += pv[i] * vv.y;
                acc[i][2] += pv[i] * vv.z;
                acc[i][3] += pv[i] * vv.w;
            }
        }
    }

    float* Og = O + base + (size_t)q0 * D_;
#pragma unroll
    for (int i = 0; i < 4; i++) {
        float inv = 1.f / li[i];
        int r = ty * 4 + i;
        float4 o;
        o.x = acc[i][0] * inv; o.y = acc[i][1] * inv;
        o.z = acc[i][2] * inv; o.w = acc[i][3] * inv;
        *(float4*)(Og + (size_t)r * D_ + tx * 4) = o;
    }
}

// ---------------------------------------------------------------------------
extern "C" void kernel_launch(void* const* d_in, const int* in_sizes, int n_in,
                              void* d_out, int out_size)
{
    const float* queries = (const float*)d_in[0];
    const float* keys    = (const float*)d_in[1];
    const float* values  = (const float*)d_in[2];
    const float* W_q = (const float*)d_in[3];
    const float* b_q = (const float*)d_in[4];
    const float* W_k = (const float*)d_in[5];
    const float* b_k = (const float*)d_in[6];
    const float* W_v = (const float*)d_in[7];
    const float* b_v = (const float*)d_in[8];
    const float* W_o = (const float*)d_in[9];
    const float* b_o = (const float*)d_in[10];
    float* out = (float*)d_out;

    float *Qp, *Kp, *Vp, *Ap;
    cudaGetSymbolAddress((void**)&Qp, g_Q);
    cudaGetSymbolAddress((void**)&Kp, g_K);
    cudaGetSymbolAddress((void**)&Vp, g_V);
    cudaGetSymbolAddress((void**)&Ap, g_A);

    const int M = B_ * S_;            // 4096
    dim3 gemm_grid(D_ / 128, M / 128);  // (8, 32)

    sgemm_nt<<<gemm_grid, 256>>>(queries, W_q, b_q, Qp, M, D_, D_);
    sgemm_nt<<<gemm_grid, 256>>>(keys,    W_k, b_k, Kp, M, D_, D_);
    sgemm_nt<<<gemm_grid, 256>>>(values,  W_v, b_v, Vp, M, D_, D_);

    const int smem = 4 * 64 * PAD * sizeof(float);  // 73728 bytes
    cudaFuncSetAttribute(attn_kernel,
                         cudaFuncAttributeMaxDynamicSharedMemorySize, smem);
    dim3 attn_grid(S_ / 64, H_, B_);  // (32, 16, 2)
    attn_kernel<<<attn_grid, 256, smem>>>(Qp, Kp, Vp, Ap);

    sgemm_nt<<<gemm_grid, 256>>>(Ap, W_o, b_o, out, M, D_, D_);
}

// round 2
// speedup vs baseline: 2.1007x; 2.1007x over previous
#include <cuda_runtime.h>
#include <cuda_bf16.h>
#include <math.h>
#include <stdint.h>

#define B_  2
#define S_  2048
#define D_  1024
#define H_  16
#define DH_ 64
#define NE_ (B_ * S_ * D_)   // 4194304 elements

// Scratch (allocation-free, __device__ globals).
// bf16 hi/lo planes stored as uint32 arrays (2 bf16 per word) for aligned access.
__device__ uint32_t g_Qh[NE_ / 2], g_Ql[NE_ / 2];   // [b][s][1024], pre-scaled by 1/8
__device__ uint32_t g_Kh[NE_ / 2], g_Kl[NE_ / 2];   // [b][s][1024]
__device__ uint32_t g_Vh[NE_ / 2], g_Vl[NE_ / 2];   // transposed: [b][h][dh(64)][s(2048)]
__device__ float    g_O[NE_];                        // attention output fp32 [b][s][1024]

// ---------------------------------------------------------------------------
// helpers
// ---------------------------------------------------------------------------
__device__ __forceinline__ void split2(float x, float y, uint32_t& hi, uint32_t& lo)
{
    __nv_bfloat162 h = __floats2bfloat162_rn(x, y);   // .x = x (low 16), .y = y (high 16)
    float rx = x - __bfloat162float(h.x);
    float ry = y - __bfloat162float(h.y);
    __nv_bfloat162 l = __floats2bfloat162_rn(rx, ry);
    hi = *reinterpret_cast<uint32_t*>(&h);
    lo = *reinterpret_cast<uint32_t*>(&l);
}

__device__ __forceinline__ void mma_bf16(float4& d,
    uint32_t a0, uint32_t a1, uint32_t a2, uint32_t a3,
    uint32_t b0, uint32_t b1)
{
    asm volatile(
        "mma.sync.aligned.m16n8k16.row.col.f32.bf16.bf16.f32 "
        "{%0,%1,%2,%3},{%4,%5,%6,%7},{%8,%9},{%0,%1,%2,%3};"
        : "+f"(d.x), "+f"(d.y), "+f"(d.z), "+f"(d.w)
        : "r"(a0), "r"(a1), "r"(a2), "r"(a3), "r"(b0), "r"(b1));
}

// ---------------------------------------------------------------------------
// GEMM (bf16x3): C[M,N] = A[M,K] @ W[N,K]^T + bias
// MODE 0: write fp32 C
// MODE 1: scale by 0.125, split, write hi/lo u32-packed planes (Q)
// MODE 2: split, write hi/lo planes (K)
// MODE 3: split, write hi/lo planes TRANSPOSED to [b][h][dh][s] (V)
// BM=128, BN=64, BK=32, 256 threads (8 warps: 4 in M x 2 in N, 32x32 each)
// ---------------------------------------------------------------------------
template <int MODE>
__global__ __launch_bounds__(256) void gemm_bf16x3(
    const float* __restrict__ A, const float* __restrict__ W,
    const float* __restrict__ bias,
    float* __restrict__ Cf, uint32_t* __restrict__ Ch, uint32_t* __restrict__ Cl,
    int M, int N, int K)
{
    __shared__ uint32_t As_h[128][20], As_l[128][20];  // [m][k-word], BK/2=16 + pad 4
    __shared__ uint32_t Ws_h[64][20],  Ws_l[64][20];

    const int tid  = threadIdx.x;
    const int lane = tid & 31;
    const int wid  = tid >> 5;
    const int wm   = wid & 3;        // warp m index 0..3
    const int wn   = wid >> 2;       // warp n index 0..1
    const int r    = lane >> 2;      // groupID
    const int c    = lane & 3;       // threadIdInGroup

    const int m_base = blockIdx.y * 128;
    const int n_base = blockIdx.x * 64;

    float4 acc[2][4];
#pragma unroll
    for (int i = 0; i < 2; i++)
#pragma unroll
        for (int j = 0; j < 4; j++) acc[i][j] = make_float4(0.f, 0.f, 0.f, 0.f);

    for (int kt = 0; kt < K; kt += 32) {
        __syncthreads();
        // load A tile 128x32
#pragma unroll
        for (int t = 0; t < 4; t++) {
            int idx = tid + t * 256;
            int rr = idx >> 3, c4 = idx & 7;
            float4 v = *(const float4*)(A + (size_t)(m_base + rr) * K + kt + c4 * 4);
            split2(v.x, v.y, As_h[rr][c4 * 2],     As_l[rr][c4 * 2]);
            split2(v.z, v.w, As_h[rr][c4 * 2 + 1], As_l[rr][c4 * 2 + 1]);
        }
        // load W tile 64x32
#pragma unroll
        for (int t = 0; t < 2; t++) {
            int idx = tid + t * 256;
            int rr = idx >> 3, c4 = idx & 7;
            float4 v = *(const float4*)(W + (size_t)(n_base + rr) * K + kt + c4 * 4);
            split2(v.x, v.y, Ws_h[rr][c4 * 2],     Ws_l[rr][c4 * 2]);
            split2(v.z, v.w, Ws_h[rr][c4 * 2 + 1], Ws_l[rr][c4 * 2 + 1]);
        }
        __syncthreads();

#pragma unroll
        for (int ks = 0; ks < 2; ks++) {
            uint32_t ah[2][4], al[2][4];
#pragma unroll
            for (int mt = 0; mt < 2; mt++) {
                int row = wm * 32 + mt * 16;
                ah[mt][0] = As_h[row + r][ks * 8 + c];
                ah[mt][1] = As_h[row + 8 + r][ks * 8 + c];
                ah[mt][2] = As_h[row + r][ks * 8 + c + 4];
                ah[mt][3] = As_h[row + 8 + r][ks * 8 + c + 4];
                al[mt][0] = As_l[row + r][ks * 8 + c];
                al[mt][1] = As_l[row + 8 + r][ks * 8 + c];
                al[mt][2] = As_l[row + r][ks * 8 + c + 4];
                al[mt][3] = As_l[row + 8 + r][ks * 8 + c + 4];
            }
#pragma unroll
            for (int nt = 0; nt < 4; nt++) {
                int coln = wn * 32 + nt * 8 + r;
                uint32_t bh0 = Ws_h[coln][ks * 8 + c];
                uint32_t bh1 = Ws_h[coln][ks * 8 + c + 4];
                uint32_t bl0 = Ws_l[coln][ks * 8 + c];
                uint32_t bl1 = Ws_l[coln][ks * 8 + c + 4];
#pragma unroll
                for (int mt = 0; mt < 2; mt++) {
                    mma_bf16(acc[mt][nt], ah[mt][0], ah[mt][1], ah[mt][2], ah[mt][3], bh0, bh1);
                    mma_bf16(acc[mt][nt], ah[mt][0], ah[mt][1], ah[mt][2], ah[mt][3], bl0, bl1);
                    mma_bf16(acc[mt][nt], al[mt][0], al[mt][1], al[mt][2], al[mt][3], bh0, bh1);
                }
            }
        }
    }

    // epilogue
#pragma unroll
    for (int mt = 0; mt < 2; mt++) {
#pragma unroll
        for (int nt = 0; nt < 4; nt++) {
            int gm0 = m_base + wm * 32 + mt * 16 + r;
            int gm1 = gm0 + 8;
            int gn  = n_base + wn * 32 + nt * 8 + c * 2;
            float b0v = bias[gn], b1v = bias[gn + 1];
            float f00 = acc[mt][nt].x + b0v, f01 = acc[mt][nt].y + b1v;
            float f10 = acc[mt][nt].z + b0v, f11 = acc[mt][nt].w + b1v;
            if (MODE == 1) { f00 *= 0.125f; f01 *= 0.125f; f10 *= 0.125f; f11 *= 0.125f; }

            if (MODE == 0) {
                *(float2*)(Cf + (size_t)gm0 * N + gn) = make_float2(f00, f01);
                *(float2*)(Cf + (size_t)gm1 * N + gn) = make_float2(f10, f11);
            } else if (MODE == 1 || MODE == 2) {
                uint32_t h0, l0, h1, l1;
                split2(f00, f01, h0, l0);
                split2(f10, f11, h1, l1);
                Ch[(size_t)gm0 * (N / 2) + gn / 2] = h0;
                Cl[(size_t)gm0 * (N / 2) + gn / 2] = l0;
                Ch[(size_t)gm1 * (N / 2) + gn / 2] = h1;
                Cl[(size_t)gm1 * (N / 2) + gn / 2] = l1;
            } else {  // MODE 3: transposed bf16 element stores
                __nv_bfloat16* Chb = (__nv_bfloat16*)Ch;
                __nv_bfloat16* Clb = (__nv_bfloat16*)Cl;
                float fv[2][2] = {{f00, f01}, {f10, f11}};
                int gms[2] = {gm0, gm1};
#pragma unroll
                for (int i = 0; i < 2; i++) {
#pragma unroll
                    for (int j = 0; j < 2; j++) {
                        int m = gms[i], n = gn + j;
                        int bb = m >> 11, s = m & 2047;
                        int hh = n >> 6, dh = n & 63;
                        size_t idx = (((size_t)(bb * H_ + hh) * DH_ + dh) * S_) + s;
                        __nv_bfloat16 hv = __float2bfloat16_rn(fv[i][j]);
                        float lvf = fv[i][j] - __bfloat162float(hv);
                        Chb[idx] = hv;
                        Clb[idx] = __float2bfloat16_rn(lvf);
                    }
                }
            }
        }
    }
}

// ---------------------------------------------------------------------------
// Flash attention via mma bf16x3. No shared memory.
// Grid: (S/128, H, B). Block 256 (8 warps). Warp w: 16 query rows.
// Per key-iter: 64 keys. Scores per warp: 16x64 (8 n-tiles).
// ---------------------------------------------------------------------------
__global__ __launch_bounds__(256) void attn_mma(
    const uint32_t* __restrict__ Qh, const uint32_t* __restrict__ Ql,
    const uint32_t* __restrict__ Kh, const uint32_t* __restrict__ Kl,
    const uint32_t* __restrict__ Vh, const uint32_t* __restrict__ Vl,
    float* __restrict__ O)
{
    const int tid  = threadIdx.x;
    const int lane = tid & 31;
    const int wid  = tid >> 5;
    const int r    = lane >> 2;
    const int c    = lane & 3;
    const int h    = blockIdx.y;
    const int b    = blockIdx.z;
    const int q0   = blockIdx.x * 128 + wid * 16;

    // u32-indexed bases (2 bf16 per word)
    const size_t qk_base = ((size_t)b * S_ * D_ + h * DH_) / 2;
    const size_t v_base  = ((size_t)(b * H_ + h) * DH_ * S_) / 2;
    const uint32_t* Qh32 = Qh + qk_base;
    const uint32_t* Ql32 = Ql + qk_base;
    const uint32_t* Kh32 = Kh + qk_base;
    const uint32_t* Kl32 = Kl + qk_base;
    const uint32_t* Vh32 = Vh + v_base;
    const uint32_t* Vl32 = Vl + v_base;

    // Q fragments, register resident (row stride in u32 = 512)
    uint32_t qh[4][4], ql[4][4];
#pragma unroll
    for (int kt = 0; kt < 4; kt++) {
        qh[kt][0] = Qh32[(size_t)(q0 + r) * 512 + kt * 8 + c];
        qh[kt][1] = Qh32[(size_t)(q0 + 8 + r) * 512 + kt * 8 + c];
        qh[kt][2] = Qh32[(size_t)(q0 + r) * 512 + kt * 8 + c + 4];
        qh[kt][3] = Qh32[(size_t)(q0 + 8 + r) * 512 + kt * 8 + c + 4];
        ql[kt][0] = Ql32[(size_t)(q0 + r) * 512 + kt * 8 + c];
        ql[kt][1] = Ql32[(size_t)(q0 + 8 + r) * 512 + kt * 8 + c];
        ql[kt][2] = Ql32[(size_t)(q0 + r) * 512 + kt * 8 + c + 4];
        ql[kt][3] = Ql32[(size_t)(q0 + 8 + r) * 512 + kt * 8 + c + 4];
    }

    float4 oacc[8];
#pragma unroll
    for (int j = 0; j < 8; j++) oacc[j] = make_float4(0.f, 0.f, 0.f, 0.f);
    float mi0 = -1e30f, mi1 = -1e30f, li0 = 0.f, li1 = 0.f;

    for (int kb = 0; kb < S_ / 64; kb++) {
        // ---- scores = Q @ K^T (pre-scaled) ----
        float4 sacc[8];
#pragma unroll
        for (int nt = 0; nt < 8; nt++) sacc[nt] = make_float4(0.f, 0.f, 0.f, 0.f);
#pragma unroll
        for (int nt = 0; nt < 8; nt++) {
            size_t krow = (size_t)(kb * 64 + nt * 8 + r) * 512;
#pragma unroll
            for (int kt = 0; kt < 4; kt++) {
                uint32_t bh0 = Kh32[krow + kt * 8 + c];
                uint32_t bh1 = Kh32[krow + kt * 8 + c + 4];
                uint32_t bl0 = Kl32[krow + kt * 8 + c];
                uint32_t bl1 = Kl32[krow + kt * 8 + c + 4];
                mma_bf16(sacc[nt], qh[kt][0], qh[kt][1], qh[kt][2], qh[kt][3], bh0, bh1);
                mma_bf16(sacc[nt], qh[kt][0], qh[kt][1], qh[kt][2], qh[kt][3], bl0, bl1);
                mma_bf16(sacc[nt], ql[kt][0], ql[kt][1], ql[kt][2], ql[kt][3], bh0, bh1);
            }
        }

        // ---- online softmax (rows r and r+8; each row fully in quad) ----
        float m0 = -1e30f, m1 = -1e30f;
#pragma unroll
        for (int nt = 0; nt < 8; nt++) {
            m0 = fmaxf(m0, fmaxf(sacc[nt].x, sacc[nt].y));
            m1 = fmaxf(m1, fmaxf(sacc[nt].z, sacc[nt].w));
        }
#pragma unroll
        for (int o = 1; o <= 2; o <<= 1) {
            m0 = fmaxf(m0, __shfl_xor_sync(0xffffffffu, m0, o));
            m1 = fmaxf(m1, __shfl_xor_sync(0xffffffffu, m1, o));
        }
        float mn0 = fmaxf(mi0, m0), mn1 = fmaxf(mi1, m1);
        float corr0 = __expf(mi0 - mn0), corr1 = __expf(mi1 - mn1);
        float rs0 = 0.f, rs1 = 0.f;
#pragma unroll
        for (int nt = 0; nt < 8; nt++) {
            sacc[nt].x = __expf(sacc[nt].x - mn0);
            sacc[nt].y = __expf(sacc[nt].y - mn0);
            sacc[nt].z = __expf(sacc[nt].z - mn1);
            sacc[nt].w = __expf(sacc[nt].w - mn1);
            rs0 += sacc[nt].x + sacc[nt].y;
            rs1 += sacc[nt].z + sacc[nt].w;
        }
#pragma unroll
        for (int o = 1; o <= 2; o <<= 1) {
            rs0 += __shfl_xor_sync(0xffffffffu, rs0, o);
            rs1 += __shfl_xor_sync(0xffffffffu, rs1, o);
        }
        li0 = li0 * corr0 + rs0;
        li1 = li1 * corr1 + rs1;
        mi0 = mn0; mi1 = mn1;
#pragma unroll
        for (int j = 0; j < 8; j++) {
            oacc[j].x *= corr0; oacc[j].y *= corr0;
            oacc[j].z *= corr1; oacc[j].w *= corr1;
        }

        // ---- P fragments (C-layout -> A-layout, register only) ----
        uint32_t ph[4][4], pl[4][4];
#pragma unroll
        for (int t = 0; t < 4; t++) {
            split2(sacc[2 * t].x,     sacc[2 * t].y,     ph[t][0], pl[t][0]);
            split2(sacc[2 * t].z,     sacc[2 * t].w,     ph[t][1], pl[t][1]);
            split2(sacc[2 * t + 1].x, sacc[2 * t + 1].y, ph[t][2], pl[t][2]);
            split2(sacc[2 * t + 1].z, sacc[2 * t + 1].w, ph[t][3], pl[t][3]);
        }

        // ---- O += P @ V  (V transposed [dh][s], k-dim = keys) ----
#pragma unroll
        for (int j = 0; j < 8; j++) {
            size_t vrow = (size_t)(j * 8 + r) * 1024;   // dh row, u32 stride = S/2
#pragma unroll
            for (int t = 0; t < 4; t++) {
                size_t kw = vrow + kb * 32 + t * 8 + c;
                uint32_t bh0 = Vh32[kw], bh1 = Vh32[kw + 4];
                uint32_t bl0 = Vl32[kw], bl1 = Vl32[kw + 4];
                mma_bf16(oacc[j], ph[t][0], ph[t][1], ph[t][2], ph[t][3], bh0, bh1);
                mma_bf16(oacc[j], ph[t][0], ph[t][1], ph[t][2], ph[t][3], bl0, bl1);
                mma_bf16(oacc[j], pl[t][0], pl[t][1], pl[t][2], pl[t][3], bh0, bh1);
            }
        }
    }

    // ---- normalize and write ----
    float inv0 = 1.f / li0, inv1 = 1.f / li1;
    float* Og = O + (size_t)b * S_ * D_ + h * DH_;
#pragma unroll
    for (int j = 0; j < 8; j++) {
        int col = j * 8 + 2 * c;
        *(float2*)(Og + (size_t)(q0 + r) * D_ + col)     = make_float2(oacc[j].x * inv0, oacc[j].y * inv0);
        *(float2*)(Og + (size_t)(q0 + 8 + r) * D_ + col) = make_float2(oacc[j].z * inv1, oacc[j].w * inv1);
    }
}

// ---------------------------------------------------------------------------
extern "C" void kernel_launch(void* const* d_in, const int* in_sizes, int n_in,
                              void* d_out, int out_size)
{
    const float* queries = (const float*)d_in[0];
    const float* keys    = (const float*)d_in[1];
    const float* values  = (const float*)d_in[2];
    const float* W_q = (const float*)d_in[3];
    const float* b_q = (const float*)d_in[4];
    const float* W_k = (const float*)d_in[5];
    const float* b_k = (const float*)d_in[6];
    const float* W_v = (const float*)d_in[7];
    const float* b_v = (const float*)d_in[8];
    const float* W_o = (const float*)d_in[9];
    const float* b_o = (const float*)d_in[10];
    float* out = (float*)d_out;

    uint32_t *Qh, *Ql, *Kh, *Kl, *Vh, *Vl;
    float* Ofp;
    cudaGetSymbolAddress((void**)&Qh, g_Qh);
    cudaGetSymbolAddress((void**)&Ql, g_Ql);
    cudaGetSymbolAddress((void**)&Kh, g_Kh);
    cudaGetSymbolAddress((void**)&Kl, g_Kl);
    cudaGetSymbolAddress((void**)&Vh, g_Vh);
    cudaGetSymbolAddress((void**)&Vl, g_Vl);
    cudaGetSymbolAddress((void**)&Ofp, g_O);

    const int M = B_ * S_;                 // 4096
    dim3 ggrid(D_ / 64, M / 128);          // (16, 32)

    gemm_bf16x3<1><<<ggrid, 256>>>(queries, W_q, b_q, nullptr, Qh, Ql, M, D_, D_);
    gemm_bf16x3<2><<<ggrid, 256>>>(keys,    W_k, b_k, nullptr, Kh, Kl, M, D_, D_);
    gemm_bf16x3<3><<<ggrid, 256>>>(values,  W_v, b_v, nullptr, Vh, Vl, M, D_, D_);

    dim3 agrid(S_ / 128, H_, B_);          // (16, 16, 2)
    attn_mma<<<agrid, 256>>>(Qh, Ql, Kh, Kl, Vh, Vl, Ofp);

    gemm_bf16x3<0><<<ggrid, 256>>>(Ofp, W_o, b_o, out, nullptr, nullptr, M, D_, D_);
}

// round 3
// speedup vs baseline: 4.5745x; 2.1776x over previous
#include <cuda_runtime.h>
#include <cuda_bf16.h>
#include <math.h>
#include <stdint.h>

#define B_  2
#define S_  2048
#define D_  1024
#define H_  16
#define DH_ 64
#define NE_ (B_ * S_ * D_)
#define NKB (S_ / 64)

// Scratch (allocation-free): bf16 hi/lo planes packed 2-per-u32.
__device__ uint32_t g_Qh[NE_ / 2], g_Ql[NE_ / 2];   // [b][s][1024], pre-scaled 1/8
__device__ uint32_t g_Kh[NE_ / 2], g_Kl[NE_ / 2];   // [b][s][1024]
__device__ uint32_t g_Vh[NE_ / 2], g_Vl[NE_ / 2];   // transposed [b][h][dh][s]
__device__ float    g_O[NE_];

// ---------------------------------------------------------------------------
__device__ __forceinline__ void split2(float x, float y, uint32_t& hi, uint32_t& lo)
{
    __nv_bfloat162 h = __floats2bfloat162_rn(x, y);
    float rx = x - __bfloat162float(h.x);
    float ry = y - __bfloat162float(h.y);
    __nv_bfloat162 l = __floats2bfloat162_rn(rx, ry);
    hi = *reinterpret_cast<uint32_t*>(&h);
    lo = *reinterpret_cast<uint32_t*>(&l);
}

__device__ __forceinline__ void mma_bf16(float4& d,
    uint32_t a0, uint32_t a1, uint32_t a2, uint32_t a3,
    uint32_t b0, uint32_t b1)
{
    asm volatile(
        "mma.sync.aligned.m16n8k16.row.col.f32.bf16.bf16.f32 "
        "{%0,%1,%2,%3},{%4,%5,%6,%7},{%8,%9},{%0,%1,%2,%3};"
        : "+f"(d.x), "+f"(d.y), "+f"(d.z), "+f"(d.w)
        : "r"(a0), "r"(a1), "r"(a2), "r"(a3), "r"(b0), "r"(b1));
}

__device__ __forceinline__ void ldsm_x4(uint32_t& r0, uint32_t& r1,
                                        uint32_t& r2, uint32_t& r3, uint32_t addr)
{
    asm volatile("ldmatrix.sync.aligned.m8n8.x4.shared.b16 {%0,%1,%2,%3}, [%4];"
                 : "=r"(r0), "=r"(r1), "=r"(r2), "=r"(r3) : "r"(addr));
}

__device__ __forceinline__ void cp16(uint32_t smaddr, const void* g)
{
    asm volatile("cp.async.cg.shared.global [%0], [%1], 16;" :: "r"(smaddr), "l"(g));
}

// ---------------------------------------------------------------------------
// GEMM (bf16x3): C[M,N] = A[M,K] @ W[N,K]^T + bias
// MODE 0: fp32 C;  1: Q (scale 1/8, split planes);  2: K planes;  3: V transposed
// BM=128 BN=64 BK=32, 256 thr, 8 warps (4m x 2n).
// ---------------------------------------------------------------------------
template <int MODE>
__global__ __launch_bounds__(256) void gemm_bf16x3(
    const float* __restrict__ A, const float* __restrict__ W,
    const float* __restrict__ bias,
    float* __restrict__ Cf, uint32_t* __restrict__ Ch, uint32_t* __restrict__ Cl,
    int M, int N, int K)
{
    __shared__ uint32_t As_h[128][20], As_l[128][20];
    __shared__ uint32_t Ws_h[64][20],  Ws_l[64][20];

    const int tid  = threadIdx.x;
    const int lane = tid & 31;
    const int wid  = tid >> 5;
    const int wm   = wid & 3;
    const int wn   = wid >> 2;
    const int r    = lane >> 2;
    const int c    = lane & 3;

    const int m_base = blockIdx.y * 128;
    const int n_base = blockIdx.x * 64;

    // ldmatrix lane geometry
    const int lrA = (lane & 7) + (((lane >> 3) & 1) << 3);
    const int lcA = (lane >> 4) * 4;
    const int lrB = (lane & 7) + ((lane >> 4) << 3);
    const int lcB = ((lane >> 3) & 1) * 4;

    uint32_t as_h_b = (uint32_t)__cvta_generic_to_shared(&As_h[0][0]);
    uint32_t as_l_b = (uint32_t)__cvta_generic_to_shared(&As_l[0][0]);
    uint32_t ws_h_b = (uint32_t)__cvta_generic_to_shared(&Ws_h[0][0]);
    uint32_t ws_l_b = (uint32_t)__cvta_generic_to_shared(&Ws_l[0][0]);

    float4 acc[2][4];
#pragma unroll
    for (int i = 0; i < 2; i++)
#pragma unroll
        for (int j = 0; j < 4; j++) acc[i][j] = make_float4(0.f, 0.f, 0.f, 0.f);

    // register prefetch of first tile
    float4 av[4], wv[2];
#pragma unroll
    for (int t = 0; t < 4; t++) {
        int idx = tid + t * 256, rr = idx >> 3, c4 = idx & 7;
        av[t] = *(const float4*)(A + (size_t)(m_base + rr) * K + c4 * 4);
    }
#pragma unroll
    for (int t = 0; t < 2; t++) {
        int idx = tid + t * 256, rr = idx >> 3, c4 = idx & 7;
        wv[t] = *(const float4*)(W + (size_t)(n_base + rr) * K + c4 * 4);
    }

    for (int kt = 0; kt < K; kt += 32) {
        // store current tile (split) into smem
#pragma unroll
        for (int t = 0; t < 4; t++) {
            int idx = tid + t * 256, rr = idx >> 3, c4 = idx & 7;
            split2(av[t].x, av[t].y, As_h[rr][c4 * 2],     As_l[rr][c4 * 2]);
            split2(av[t].z, av[t].w, As_h[rr][c4 * 2 + 1], As_l[rr][c4 * 2 + 1]);
        }
#pragma unroll
        for (int t = 0; t < 2; t++) {
            int idx = tid + t * 256, rr = idx >> 3, c4 = idx & 7;
            split2(wv[t].x, wv[t].y, Ws_h[rr][c4 * 2],     Ws_l[rr][c4 * 2]);
            split2(wv[t].z, wv[t].w, Ws_h[rr][c4 * 2 + 1], Ws_l[rr][c4 * 2 + 1]);
        }
        __syncthreads();

        // prefetch next tile
        if (kt + 32 < K) {
#pragma unroll
            for (int t = 0; t < 4; t++) {
                int idx = tid + t * 256, rr = idx >> 3, c4 = idx & 7;
                av[t] = *(const float4*)(A + (size_t)(m_base + rr) * K + kt + 32 + c4 * 4);
            }
#pragma unroll
            for (int t = 0; t < 2; t++) {
                int idx = tid + t * 256, rr = idx >> 3, c4 = idx & 7;
                wv[t] = *(const float4*)(W + (size_t)(n_base + rr) * K + kt + 32 + c4 * 4);
            }
        }

#pragma unroll
        for (int ks = 0; ks < 2; ks++) {
            uint32_t ah[2][4], al[2][4];
#pragma unroll
            for (int mt = 0; mt < 2; mt++) {
                uint32_t o = ((wm * 32 + mt * 16 + lrA) * 20 + ks * 8 + lcA) * 4;
                ldsm_x4(ah[mt][0], ah[mt][1], ah[mt][2], ah[mt][3], as_h_b + o);
                ldsm_x4(al[mt][0], al[mt][1], al[mt][2], al[mt][3], as_l_b + o);
            }
#pragma unroll
            for (int ntp = 0; ntp < 2; ntp++) {
                uint32_t o = ((wn * 32 + ntp * 16 + lrB) * 20 + ks * 8 + lcB) * 4;
                uint32_t bh0, bh1, bh2, bh3, bl0, bl1, bl2, bl3;
                ldsm_x4(bh0, bh1, bh2, bh3, ws_h_b + o);
                ldsm_x4(bl0, bl1, bl2, bl3, ws_l_b + o);
#pragma unroll
                for (int mt = 0; mt < 2; mt++) {
                    mma_bf16(acc[mt][2 * ntp],     ah[mt][0], ah[mt][1], ah[mt][2], ah[mt][3], bh0, bh1);
                    mma_bf16(acc[mt][2 * ntp],     ah[mt][0], ah[mt][1], ah[mt][2], ah[mt][3], bl0, bl1);
                    mma_bf16(acc[mt][2 * ntp],     al[mt][0], al[mt][1], al[mt][2], al[mt][3], bh0, bh1);
                    mma_bf16(acc[mt][2 * ntp + 1], ah[mt][0], ah[mt][1], ah[mt][2], ah[mt][3], bh2, bh3);
                    mma_bf16(acc[mt][2 * ntp + 1], ah[mt][0], ah[mt][1], ah[mt][2], ah[mt][3], bl2, bl3);
                    mma_bf16(acc[mt][2 * ntp + 1], al[mt][0], al[mt][1], al[mt][2], al[mt][3], bh2, bh3);
                }
            }
        }
        __syncthreads();
    }

    // epilogue
#pragma unroll
    for (int mt = 0; mt < 2; mt++) {
#pragma unroll
        for (int nt = 0; nt < 4; nt++) {
            int gm0 = m_base + wm * 32 + mt * 16 + r;
            int gm1 = gm0 + 8;
            int gn  = n_base + wn * 32 + nt * 8 + c * 2;
            float b0v = bias[gn], b1v = bias[gn + 1];
            float f00 = acc[mt][nt].x + b0v, f01 = acc[mt][nt].y + b1v;
            float f10 = acc[mt][nt].z + b0v, f11 = acc[mt][nt].w + b1v;
            if (MODE == 1) { f00 *= 0.125f; f01 *= 0.125f; f10 *= 0.125f; f11 *= 0.125f; }

            if (MODE == 0) {
                *(float2*)(Cf + (size_t)gm0 * N + gn) = make_float2(f00, f01);
                *(float2*)(Cf + (size_t)gm1 * N + gn) = make_float2(f10, f11);
            } else if (MODE == 1 || MODE == 2) {
                uint32_t h0, l0, h1, l1;
                split2(f00, f01, h0, l0);
                split2(f10, f11, h1, l1);
                Ch[(size_t)gm0 * (N / 2) + gn / 2] = h0;
                Cl[(size_t)gm0 * (N / 2) + gn / 2] = l0;
                Ch[(size_t)gm1 * (N / 2) + gn / 2] = h1;
                Cl[(size_t)gm1 * (N / 2) + gn / 2] = l1;
            } else {
                __nv_bfloat16* Chb = (__nv_bfloat16*)Ch;
                __nv_bfloat16* Clb = (__nv_bfloat16*)Cl;
                float fv[2][2] = {{f00, f01}, {f10, f11}};
                int gms[2] = {gm0, gm1};
#pragma unroll
                for (int i = 0; i < 2; i++)
#pragma unroll
                    for (int j = 0; j < 2; j++) {
                        int m = gms[i], n = gn + j;
                        int bb = m >> 11, s = m & 2047;
                        int hh = n >> 6, dh = n & 63;
                        size_t idx = (((size_t)(bb * H_ + hh) * DH_ + dh) * S_) + s;
                        __nv_bfloat16 hv = __float2bfloat16_rn(fv[i][j]);
                        float lvf = fv[i][j] - __bfloat162float(hv);
                        Chb[idx] = hv;
                        Clb[idx] = __float2bfloat16_rn(lvf);
                    }
            }
        }
    }
}

// ---------------------------------------------------------------------------
// Flash attention, mma bf16x3, smem-staged K/V (cp.async double buffer),
// ldmatrix fragment loads. Grid (S/128, H, B), 256 thr, warp = 16 q-rows.
// Dyn smem: 2 bufs x 4 planes x 64 rows x 36 u32 = 73728 B.
// ---------------------------------------------------------------------------
__global__ __launch_bounds__(256, 2) void attn_mma(
    const uint32_t* __restrict__ Qh, const uint32_t* __restrict__ Ql,
    const uint32_t* __restrict__ Kh, const uint32_t* __restrict__ Kl,
    const uint32_t* __restrict__ Vh, const uint32_t* __restrict__ Vl,
    float* __restrict__ O)
{
    extern __shared__ uint32_t smu[];
    const int tid  = threadIdx.x;
    const int lane = tid & 31;
    const int wid  = tid >> 5;
    const int r    = lane >> 2;
    const int c    = lane & 3;
    const int h    = blockIdx.y;
    const int b    = blockIdx.z;
    const int q0   = blockIdx.x * 128 + wid * 16;

    const size_t qk_base = ((size_t)b * S_ * D_ + h * DH_) / 2;
    const size_t v_base  = ((size_t)(b * H_ + h) * DH_ * S_) / 2;
    const uint32_t* Qh32 = Qh + qk_base;
    const uint32_t* Ql32 = Ql + qk_base;
    const uint32_t* Kh32 = Kh + qk_base;
    const uint32_t* Kl32 = Kl + qk_base;
    const uint32_t* Vh32 = Vh + v_base;
    const uint32_t* Vl32 = Vl + v_base;

    const uint32_t sbase = (uint32_t)__cvta_generic_to_shared(smu);
    // lane geometry for B-fragment ldmatrix
    const int lr  = (lane & 7) + ((lane >> 4) << 3);
    const int lc4 = ((lane >> 3) & 1) * 4;
    const uint32_t laddr = (uint32_t)(lr * 36 + lc4) * 4;

    // Q fragments (register resident)
    uint32_t qh[4][4], ql[4][4];
#pragma unroll
    for (int kt = 0; kt < 4; kt++) {
        qh[kt][0] = Qh32[(size_t)(q0 + r) * 512 + kt * 8 + c];
        qh[kt][1] = Qh32[(size_t)(q0 + 8 + r) * 512 + kt * 8 + c];
        qh[kt][2] = Qh32[(size_t)(q0 + r) * 512 + kt * 8 + c + 4];
        qh[kt][3] = Qh32[(size_t)(q0 + 8 + r) * 512 + kt * 8 + c + 4];
        ql[kt][0] = Ql32[(size_t)(q0 + r) * 512 + kt * 8 + c];
        ql[kt][1] = Ql32[(size_t)(q0 + 8 + r) * 512 + kt * 8 + c];
        ql[kt][2] = Ql32[(size_t)(q0 + r) * 512 + kt * 8 + c + 4];
        ql[kt][3] = Ql32[(size_t)(q0 + 8 + r) * 512 + kt * 8 + c + 4];
    }

    float4 oacc[8];
#pragma unroll
    for (int j = 0; j < 8; j++) oacc[j] = make_float4(0.f, 0.f, 0.f, 0.f);
    float mi0 = -1e30f, mi1 = -1e30f, li0 = 0.f, li1 = 0.f;

    // stage loader: 4 planes, 2 x uint4 per thread per plane
    auto prefetch = [&](int kb) {
        uint32_t bufb = sbase + (uint32_t)(kb & 1) * 9216 * 4;
#pragma unroll
        for (int t = 0; t < 2; t++) {
            int i = tid + t * 256;
            int row = i >> 3, col = (i & 7) * 4;
            uint32_t off = (uint32_t)(row * 36 + col) * 4;
            size_t kg = (size_t)(kb * 64 + row) * 512 + col;
            size_t vg = (size_t)row * 1024 + kb * 32 + col;
            cp16(bufb + off,            Kh32 + kg);
            cp16(bufb + 2304 * 4 + off, Kl32 + kg);
            cp16(bufb + 4608 * 4 + off, Vh32 + vg);
            cp16(bufb + 6912 * 4 + off, Vl32 + vg);
        }
        asm volatile("cp.async.commit_group;" ::: "memory");
    };

    prefetch(0);

    for (int kb = 0; kb < NKB; kb++) {
        if (kb + 1 < NKB) {
            prefetch(kb + 1);
            asm volatile("cp.async.wait_group 1;" ::: "memory");
        } else {
            asm volatile("cp.async.wait_group 0;" ::: "memory");
        }
        __syncthreads();

        uint32_t bufb = sbase + (uint32_t)(kb & 1) * 9216 * 4;
        uint32_t kh_b = bufb, kl_b = bufb + 2304 * 4;
        uint32_t vh_b = bufb + 4608 * 4, vl_b = bufb + 6912 * 4;

        // ---- scores = Q @ K^T ----
        float4 sacc[8];
#pragma unroll
        for (int nt = 0; nt < 8; nt++) sacc[nt] = make_float4(0.f, 0.f, 0.f, 0.f);
#pragma unroll
        for (int ng = 0; ng < 4; ng++) {
#pragma unroll
            for (int kt = 0; kt < 4; kt++) {
                uint32_t o = laddr + (uint32_t)(ng * 576 + kt * 8) * 4;
                uint32_t h0, h1, h2, h3, l0, l1, l2, l3;
                ldsm_x4(h0, h1, h2, h3, kh_b + o);
                ldsm_x4(l0, l1, l2, l3, kl_b + o);
                mma_bf16(sacc[2 * ng],     qh[kt][0], qh[kt][1], qh[kt][2], qh[kt][3], h0, h1);
                mma_bf16(sacc[2 * ng],     qh[kt][0], qh[kt][1], qh[kt][2], qh[kt][3], l0, l1);
                mma_bf16(sacc[2 * ng],     ql[kt][0], ql[kt][1], ql[kt][2], ql[kt][3], h0, h1);
                mma_bf16(sacc[2 * ng + 1], qh[kt][0], qh[kt][1], qh[kt][2], qh[kt][3], h2, h3);
                mma_bf16(sacc[2 * ng + 1], qh[kt][0], qh[kt][1], qh[kt][2], qh[kt][3], l2, l3);
                mma_bf16(sacc[2 * ng + 1], ql[kt][0], ql[kt][1], ql[kt][2], ql[kt][3], h2, h3);
            }
        }

        // ---- online softmax (rows r, r+8) ----
        float m0 = -1e30f, m1 = -1e30f;
#pragma unroll
        for (int nt = 0; nt < 8; nt++) {
            m0 = fmaxf(m0, fmaxf(sacc[nt].x, sacc[nt].y));
            m1 = fmaxf(m1, fmaxf(sacc[nt].z, sacc[nt].w));
        }
#pragma unroll
        for (int o = 1; o <= 2; o <<= 1) {
            m0 = fmaxf(m0, __shfl_xor_sync(0xffffffffu, m0, o));
            m1 = fmaxf(m1, __shfl_xor_sync(0xffffffffu, m1, o));
        }
        float mn0 = fmaxf(mi0, m0), mn1 = fmaxf(mi1, m1);
        float corr0 = __expf(mi0 - mn0), corr1 = __expf(mi1 - mn1);
        float rs0 = 0.f, rs1 = 0.f;
#pragma unroll
        for (int nt = 0; nt < 8; nt++) {
            sacc[nt].x = __expf(sacc[nt].x - mn0);
            sacc[nt].y = __expf(sacc[nt].y - mn0);
            sacc[nt].z = __expf(sacc[nt].z - mn1);
            sacc[nt].w = __expf(sacc[nt].w - mn1);
            rs0 += sacc[nt].x + sacc[nt].y;
            rs1 += sacc[nt].z + sacc[nt].w;
        }
#pragma unroll
        for (int o = 1; o <= 2; o <<= 1) {
            rs0 += __shfl_xor_sync(0xffffffffu, rs0, o);
            rs1 += __shfl_xor_sync(0xffffffffu, rs1, o);
        }
        li0 = li0 * corr0 + rs0;
        li1 = li1 * corr1 + rs1;
        mi0 = mn0; mi1 = mn1;
#pragma unroll
        for (int j = 0; j < 8; j++) {
            oacc[j].x *= corr0; oacc[j].y *= corr0;
            oacc[j].z *= corr1; oacc[j].w *= corr1;
        }

        // ---- P fragments ----
        uint32_t ph[4][4], pl[4][4];
#pragma unroll
        for (int t = 0; t < 4; t++) {
            split2(sacc[2 * t].x,     sacc[2 * t].y,     ph[t][0], pl[t][0]);
            split2(sacc[2 * t].z,     sacc[2 * t].w,     ph[t][1], pl[t][1]);
            split2(sacc[2 * t + 1].x, sacc[2 * t + 1].y, ph[t][2], pl[t][2]);
            split2(sacc[2 * t + 1].z, sacc[2 * t + 1].w, ph[t][3], pl[t][3]);
        }

        // ---- O += P @ V ----
#pragma unroll
        for (int jg = 0; jg < 4; jg++) {
#pragma unroll
            for (int kt = 0; kt < 4; kt++) {
                uint32_t o = laddr + (uint32_t)(jg * 576 + kt * 8) * 4;
                uint32_t h0, h1, h2, h3, l0, l1, l2, l3;
                ldsm_x4(h0, h1, h2, h3, vh_b + o);
                ldsm_x4(l0, l1, l2, l3, vl_b + o);
                mma_bf16(oacc[2 * jg],     ph[kt][0], ph[kt][1], ph[kt][2], ph[kt][3], h0, h1);
                mma_bf16(oacc[2 * jg],     ph[kt][0], ph[kt][1], ph[kt][2], ph[kt][3], l0, l1);
                mma_bf16(oacc[2 * jg],     pl[kt][0], pl[kt][1], pl[kt][2], pl[kt][3], h0, h1);
                mma_bf16(oacc[2 * jg + 1], ph[kt][0], ph[kt][1], ph[kt][2], ph[kt][3], h2, h3);
                mma_bf16(oacc[2 * jg + 1], ph[kt][0], ph[kt][1], ph[kt][2], ph[kt][3], l2, l3);
                mma_bf16(oacc[2 * jg + 1], pl[kt][0], pl[kt][1], pl[kt][2], pl[kt][3], h2, h3);
            }
        }
        __syncthreads();
    }

    // ---- normalize and write ----
    float inv0 = 1.f / li0, inv1 = 1.f / li1;
    float* Og = O + (size_t)b * S_ * D_ + h * DH_;
#pragma unroll
    for (int j = 0; j < 8; j++) {
        int col = j * 8 + 2 * c;
        *(float2*)(Og + (size_t)(q0 + r) * D_ + col)     = make_float2(oacc[j].x * inv0, oacc[j].y * inv0);
        *(float2*)(Og + (size_t)(q0 + 8 + r) * D_ + col) = make_float2(oacc[j].z * inv1, oacc[j].w * inv1);
    }
}

// ---------------------------------------------------------------------------
extern "C" void kernel_launch(void* const* d_in, const int* in_sizes, int n_in,
                              void* d_out, int out_size)
{
    const float* queries = (const float*)d_in[0];
    const float* keys    = (const float*)d_in[1];
    const float* values  = (const float*)d_in[2];
    const float* W_q = (const float*)d_in[3];
    const float* b_q = (const float*)d_in[4];
    const float* W_k = (const float*)d_in[5];
    const float* b_k = (const float*)d_in[6];
    const float* W_v = (const float*)d_in[7];
    const float* b_v = (const float*)d_in[8];
    const float* W_o = (const float*)d_in[9];
    const float* b_o = (const float*)d_in[10];
    float* out = (float*)d_out;

    uint32_t *Qh, *Ql, *Kh, *Kl, *Vh, *Vl;
    float* Ofp;
    cudaGetSymbolAddress((void**)&Qh, g_Qh);
    cudaGetSymbolAddress((void**)&Ql, g_Ql);
    cudaGetSymbolAddress((void**)&Kh, g_Kh);
    cudaGetSymbolAddress((void**)&Kl, g_Kl);
    cudaGetSymbolAddress((void**)&Vh, g_Vh);
    cudaGetSymbolAddress((void**)&Vl, g_Vl);
    cudaGetSymbolAddress((void**)&Ofp, g_O);

    const int M = B_ * S_;
    dim3 ggrid(D_ / 64, M / 128);

    gemm_bf16x3<1><<<ggrid, 256>>>(queries, W_q, b_q, nullptr, Qh, Ql, M, D_, D_);
    gemm_bf16x3<2><<<ggrid, 256>>>(keys,    W_k, b_k, nullptr, Kh, Kl, M, D_, D_);
    gemm_bf16x3<3><<<ggrid, 256>>>(values,  W_v, b_v, nullptr, Vh, Vl, M, D_, D_);

    const int smem = 2 * 4 * 64 * 36 * 4;   // 73728
    cudaFuncSetAttribute(attn_mma, cudaFuncAttributeMaxDynamicSharedMemorySize, smem);
    dim3 agrid(S_ / 128, H_, B_);
    attn_mma<<<agrid, 256, smem>>>(Qh, Ql, Kh, Kl, Vh, Vl, Ofp);

    gemm_bf16x3<0><<<ggrid, 256>>>(Ofp, W_o, b_o, out, nullptr, nullptr, M, D_, D_);
}

// round 4
// speedup vs baseline: 4.6617x; 1.0191x over previous
#include <cuda_runtime.h>
#include <cuda_bf16.h>
#include <math.h>
#include <stdint.h>

#define B_  2
#define S_  2048
#define D_  1024
#define H_  16
#define DH_ 64
#define NE_ (B_ * S_ * D_)
#define NKB (S_ / 64)

// Scratch (allocation-free): bf16 hi/lo planes packed 2-per-u32.
__device__ uint32_t g_Qh[NE_ / 2], g_Ql[NE_ / 2];   // proj Q [b][s][1024], pre-scaled 1/8
__device__ uint32_t g_Kh[NE_ / 2], g_Kl[NE_ / 2];   // proj K
__device__ uint32_t g_Vh[NE_ / 2], g_Vl[NE_ / 2];   // proj V transposed [b][h][dh][s]
__device__ uint32_t g_AOh[NE_ / 2], g_AOl[NE_ / 2]; // attention output planes
__device__ uint32_t g_Xh[NE_ / 2], g_Xl[NE_ / 2];   // split activation (reused)
__device__ uint32_t g_Wh[D_ * D_ / 2], g_Wl[D_ * D_ / 2]; // split weight (reused)

// ---------------------------------------------------------------------------
__device__ __forceinline__ void split2(float x, float y, uint32_t& hi, uint32_t& lo)
{
    __nv_bfloat162 h = __floats2bfloat162_rn(x, y);
    float rx = x - __bfloat162float(h.x);
    float ry = y - __bfloat162float(h.y);
    __nv_bfloat162 l = __floats2bfloat162_rn(rx, ry);
    hi = *reinterpret_cast<uint32_t*>(&h);
    lo = *reinterpret_cast<uint32_t*>(&l);
}

__device__ __forceinline__ void mma_bf16(float4& d,
    uint32_t a0, uint32_t a1, uint32_t a2, uint32_t a3,
    uint32_t b0, uint32_t b1)
{
    asm volatile(
        "mma.sync.aligned.m16n8k16.row.col.f32.bf16.bf16.f32 "
        "{%0,%1,%2,%3},{%4,%5,%6,%7},{%8,%9},{%0,%1,%2,%3};"
        : "+f"(d.x), "+f"(d.y), "+f"(d.z), "+f"(d.w)
        : "r"(a0), "r"(a1), "r"(a2), "r"(a3), "r"(b0), "r"(b1));
}

__device__ __forceinline__ void ldsm_x4(uint32_t& r0, uint32_t& r1,
                                        uint32_t& r2, uint32_t& r3, uint32_t addr)
{
    asm volatile("ldmatrix.sync.aligned.m8n8.x4.shared.b16 {%0,%1,%2,%3}, [%4];"
                 : "=r"(r0), "=r"(r1), "=r"(r2), "=r"(r3) : "r"(addr));
}

__device__ __forceinline__ void cp16(uint32_t smaddr, const void* g)
{
    asm volatile("cp.async.cg.shared.global [%0], [%1], 16;" :: "r"(smaddr), "l"(g));
}

// ---------------------------------------------------------------------------
// Split fp32 -> bf16 hi/lo planes. n4 = elements/4.
// ---------------------------------------------------------------------------
__global__ __launch_bounds__(256) void split_kernel(
    const float* __restrict__ src, uint32_t* __restrict__ hi,
    uint32_t* __restrict__ lo, int n4)
{
    int i = blockIdx.x * 256 + threadIdx.x;
    if (i >= n4) return;
    float4 v = ((const float4*)src)[i];
    uint32_t h0, l0, h1, l1;
    split2(v.x, v.y, h0, l0);
    split2(v.z, v.w, h1, l1);
    ((uint2*)hi)[i] = make_uint2(h0, h1);
    ((uint2*)lo)[i] = make_uint2(l0, l1);
}

// ---------------------------------------------------------------------------
// Pure-bf16x3 GEMM from pre-split planes.
// C[M,N] = A[M,K] @ W[N,K]^T + bias
// MODE 0: fp32 C;  1: Q (scale 1/8, split planes);  2: split planes;
// MODE 3: split planes transposed [b][h][dh][s].
// BM=128 BN=64 BK=32, 256 thr, 8 warps (4m x 2n). cp.async double buffer.
// Dyn smem: 2 stages x 7680 u32 = 61440 B.
// ---------------------------------------------------------------------------
#define STG_U32 7680u
#define AL_OFF  (2560u * 4u)
#define WH_OFF  (5120u * 4u)
#define WL_OFF  (6400u * 4u)

template <int MODE>
__global__ __launch_bounds__(256) void gemm_planes(
    const uint32_t* __restrict__ Ah, const uint32_t* __restrict__ Al,
    const uint32_t* __restrict__ Wh, const uint32_t* __restrict__ Wl,
    const float* __restrict__ bias,
    float* __restrict__ Cf, uint32_t* __restrict__ Ch, uint32_t* __restrict__ Cl,
    int M, int N, int K)
{
    extern __shared__ uint32_t sg[];
    const uint32_t sb = (uint32_t)__cvta_generic_to_shared(sg);

    const int tid  = threadIdx.x;
    const int lane = tid & 31;
    const int wid  = tid >> 5;
    const int wm   = wid & 3;
    const int wn   = wid >> 2;
    const int r    = lane >> 2;
    const int c    = lane & 3;

    const int m_base = blockIdx.y * 128;
    const int n_base = blockIdx.x * 64;
    const int KW = K >> 1;            // u32 words per row

    const int lrA = (lane & 7) + (((lane >> 3) & 1) << 3);
    const int lcA = (lane >> 4) * 4;
    const int lrB = (lane & 7) + ((lane >> 4) << 3);
    const int lcB = ((lane >> 3) & 1) * 4;

    // loader geometry
    const int arr0 = (tid >> 2),     ach = (tid & 3) * 4;          // A rows 0..63
    const int arr1 = (tid >> 2) + 64;                              // A rows 64..127
    const int wrr  = (tid >> 2);                                   // W rows 0..63

    auto prefetch = [&](int ktile) {
        uint32_t base = sb + (uint32_t)(ktile & 1) * STG_U32 * 4u;
        int ktw = ktile * 16;
        const uint32_t* a_h0 = Ah + (size_t)(m_base + arr0) * KW + ktw + ach;
        const uint32_t* a_l0 = Al + (size_t)(m_base + arr0) * KW + ktw + ach;
        const uint32_t* a_h1 = Ah + (size_t)(m_base + arr1) * KW + ktw + ach;
        const uint32_t* a_l1 = Al + (size_t)(m_base + arr1) * KW + ktw + ach;
        const uint32_t* w_h  = Wh + (size_t)(n_base + wrr) * KW + ktw + ach;
        const uint32_t* w_l  = Wl + (size_t)(n_base + wrr) * KW + ktw + ach;
        uint32_t o0 = (uint32_t)(arr0 * 20 + ach) * 4u;
        uint32_t o1 = (uint32_t)(arr1 * 20 + ach) * 4u;
        uint32_t ow = (uint32_t)(wrr * 20 + ach) * 4u;
        cp16(base + o0,          a_h0);
        cp16(base + AL_OFF + o0, a_l0);
        cp16(base + o1,          a_h1);
        cp16(base + AL_OFF + o1, a_l1);
        cp16(base + WH_OFF + ow, w_h);
        cp16(base + WL_OFF + ow, w_l);
        asm volatile("cp.async.commit_group;" ::: "memory");
    };

    float4 acc[2][4];
#pragma unroll
    for (int i = 0; i < 2; i++)
#pragma unroll
        for (int j = 0; j < 4; j++) acc[i][j] = make_float4(0.f, 0.f, 0.f, 0.f);

    const int NT = K / 32;
    prefetch(0);

    for (int kt = 0; kt < NT; kt++) {
        if (kt + 1 < NT) {
            prefetch(kt + 1);
            asm volatile("cp.async.wait_group 1;" ::: "memory");
        } else {
            asm volatile("cp.async.wait_group 0;" ::: "memory");
        }
        __syncthreads();

        uint32_t base = sb + (uint32_t)(kt & 1) * STG_U32 * 4u;

#pragma unroll
        for (int ks = 0; ks < 2; ks++) {
            uint32_t ah[2][4], al[2][4];
#pragma unroll
            for (int mt = 0; mt < 2; mt++) {
                uint32_t o = (uint32_t)((wm * 32 + mt * 16 + lrA) * 20 + ks * 8 + lcA) * 4u;
                ldsm_x4(ah[mt][0], ah[mt][1], ah[mt][2], ah[mt][3], base + o);
                ldsm_x4(al[mt][0], al[mt][1], al[mt][2], al[mt][3], base + AL_OFF + o);
            }
#pragma unroll
            for (int ntp = 0; ntp < 2; ntp++) {
                uint32_t o = (uint32_t)((wn * 32 + ntp * 16 + lrB) * 20 + ks * 8 + lcB) * 4u;
                uint32_t bh0, bh1, bh2, bh3, bl0, bl1, bl2, bl3;
                ldsm_x4(bh0, bh1, bh2, bh3, base + WH_OFF + o);
                ldsm_x4(bl0, bl1, bl2, bl3, base + WL_OFF + o);
#pragma unroll
                for (int mt = 0; mt < 2; mt++) {
                    mma_bf16(acc[mt][2 * ntp],     ah[mt][0], ah[mt][1], ah[mt][2], ah[mt][3], bh0, bh1);
                    mma_bf16(acc[mt][2 * ntp],     ah[mt][0], ah[mt][1], ah[mt][2], ah[mt][3], bl0, bl1);
                    mma_bf16(acc[mt][2 * ntp],     al[mt][0], al[mt][1], al[mt][2], al[mt][3], bh0, bh1);
                    mma_bf16(acc[mt][2 * ntp + 1], ah[mt][0], ah[mt][1], ah[mt][2], ah[mt][3], bh2, bh3);
                    mma_bf16(acc[mt][2 * ntp + 1], ah[mt][0], ah[mt][1], ah[mt][2], ah[mt][3], bl2, bl3);
                    mma_bf16(acc[mt][2 * ntp + 1], al[mt][0], al[mt][1], al[mt][2], al[mt][3], bh2, bh3);
                }
            }
        }
        __syncthreads();
    }

    // epilogue
#pragma unroll
    for (int mt = 0; mt < 2; mt++) {
#pragma unroll
        for (int nt = 0; nt < 4; nt++) {
            int gm0 = m_base + wm * 32 + mt * 16 + r;
            int gm1 = gm0 + 8;
            int gn  = n_base + wn * 32 + nt * 8 + c * 2;
            float b0v = bias[gn], b1v = bias[gn + 1];
            float f00 = acc[mt][nt].x + b0v, f01 = acc[mt][nt].y + b1v;
            float f10 = acc[mt][nt].z + b0v, f11 = acc[mt][nt].w + b1v;
            if (MODE == 1) { f00 *= 0.125f; f01 *= 0.125f; f10 *= 0.125f; f11 *= 0.125f; }

            if (MODE == 0) {
                *(float2*)(Cf + (size_t)gm0 * N + gn) = make_float2(f00, f01);
                *(float2*)(Cf + (size_t)gm1 * N + gn) = make_float2(f10, f11);
            } else if (MODE == 1 || MODE == 2) {
                uint32_t h0, l0, h1, l1;
                split2(f00, f01, h0, l0);
                split2(f10, f11, h1, l1);
                Ch[(size_t)gm0 * (N / 2) + gn / 2] = h0;
                Cl[(size_t)gm0 * (N / 2) + gn / 2] = l0;
                Ch[(size_t)gm1 * (N / 2) + gn / 2] = h1;
                Cl[(size_t)gm1 * (N / 2) + gn / 2] = l1;
            } else {
                __nv_bfloat16* Chb = (__nv_bfloat16*)Ch;
                __nv_bfloat16* Clb = (__nv_bfloat16*)Cl;
                float fv[2][2] = {{f00, f01}, {f10, f11}};
                int gms[2] = {gm0, gm1};
#pragma unroll
                for (int i = 0; i < 2; i++)
#pragma unroll
                    for (int j = 0; j < 2; j++) {
                        int m = gms[i], n = gn + j;
                        int bb = m >> 11, s = m & 2047;
                        int hh = n >> 6, dh = n & 63;
                        size_t idx = (((size_t)(bb * H_ + hh) * DH_ + dh) * S_) + s;
                        __nv_bfloat16 hv = __float2bfloat16_rn(fv[i][j]);
                        float lvf = fv[i][j] - __bfloat162float(hv);
                        Chb[idx] = hv;
                        Clb[idx] = __float2bfloat16_rn(lvf);
                    }
            }
        }
    }
}

// ---------------------------------------------------------------------------
// Flash attention, mma bf16x3, smem-staged K/V (cp.async double buffer),
// ldmatrix fragment loads. Output written as split planes.
// ---------------------------------------------------------------------------
__global__ __launch_bounds__(256, 2) void attn_mma(
    const uint32_t* __restrict__ Qh, const uint32_t* __restrict__ Ql,
    const uint32_t* __restrict__ Kh, const uint32_t* __restrict__ Kl,
    const uint32_t* __restrict__ Vh, const uint32_t* __restrict__ Vl,
    uint32_t* __restrict__ AOh, uint32_t* __restrict__ AOl)
{
    extern __shared__ uint32_t smu[];
    const int tid  = threadIdx.x;
    const int lane = tid & 31;
    const int wid  = tid >> 5;
    const int r    = lane >> 2;
    const int c    = lane & 3;
    const int h    = blockIdx.y;
    const int b    = blockIdx.z;
    const int q0   = blockIdx.x * 128 + wid * 16;

    const size_t qk_base = ((size_t)b * S_ * D_ + h * DH_) / 2;
    const size_t v_base  = ((size_t)(b * H_ + h) * DH_ * S_) / 2;
    const uint32_t* Qh32 = Qh + qk_base;
    const uint32_t* Ql32 = Ql + qk_base;
    const uint32_t* Kh32 = Kh + qk_base;
    const uint32_t* Kl32 = Kl + qk_base;
    const uint32_t* Vh32 = Vh + v_base;
    const uint32_t* Vl32 = Vl + v_base;

    const uint32_t sbase = (uint32_t)__cvta_generic_to_shared(smu);
    const int lr  = (lane & 7) + ((lane >> 4) << 3);
    const int lc4 = ((lane >> 3) & 1) * 4;
    const uint32_t laddr = (uint32_t)(lr * 36 + lc4) * 4;

    uint32_t qh[4][4], ql[4][4];
#pragma unroll
    for (int kt = 0; kt < 4; kt++) {
        qh[kt][0] = Qh32[(size_t)(q0 + r) * 512 + kt * 8 + c];
        qh[kt][1] = Qh32[(size_t)(q0 + 8 + r) * 512 + kt * 8 + c];
        qh[kt][2] = Qh32[(size_t)(q0 + r) * 512 + kt * 8 + c + 4];
        qh[kt][3] = Qh32[(size_t)(q0 + 8 + r) * 512 + kt * 8 + c + 4];
        ql[kt][0] = Ql32[(size_t)(q0 + r) * 512 + kt * 8 + c];
        ql[kt][1] = Ql32[(size_t)(q0 + 8 + r) * 512 + kt * 8 + c];
        ql[kt][2] = Ql32[(size_t)(q0 + r) * 512 + kt * 8 + c + 4];
        ql[kt][3] = Ql32[(size_t)(q0 + 8 + r) * 512 + kt * 8 + c + 4];
    }

    float4 oacc[8];
#pragma unroll
    for (int j = 0; j < 8; j++) oacc[j] = make_float4(0.f, 0.f, 0.f, 0.f);
    float mi0 = -1e30f, mi1 = -1e30f, li0 = 0.f, li1 = 0.f;

    auto prefetch = [&](int kb) {
        uint32_t bufb = sbase + (uint32_t)(kb & 1) * 9216 * 4;
#pragma unroll
        for (int t = 0; t < 2; t++) {
            int i = tid + t * 256;
            int row = i >> 3, col = (i & 7) * 4;
            uint32_t off = (uint32_t)(row * 36 + col) * 4;
            size_t kg = (size_t)(kb * 64 + row) * 512 + col;
            size_t vg = (size_t)row * 1024 + kb * 32 + col;
            cp16(bufb + off,            Kh32 + kg);
            cp16(bufb + 2304 * 4 + off, Kl32 + kg);
            cp16(bufb + 4608 * 4 + off, Vh32 + vg);
            cp16(bufb + 6912 * 4 + off, Vl32 + vg);
        }
        asm volatile("cp.async.commit_group;" ::: "memory");
    };

    prefetch(0);

    for (int kb = 0; kb < NKB; kb++) {
        if (kb + 1 < NKB) {
            prefetch(kb + 1);
            asm volatile("cp.async.wait_group 1;" ::: "memory");
        } else {
            asm volatile("cp.async.wait_group 0;" ::: "memory");
        }
        __syncthreads();

        uint32_t bufb = sbase + (uint32_t)(kb & 1) * 9216 * 4;
        uint32_t kh_b = bufb, kl_b = bufb + 2304 * 4;
        uint32_t vh_b = bufb + 4608 * 4, vl_b = bufb + 6912 * 4;

        float4 sacc[8];
#pragma unroll
        for (int nt = 0; nt < 8; nt++) sacc[nt] = make_float4(0.f, 0.f, 0.f, 0.f);
#pragma unroll
        for (int ng = 0; ng < 4; ng++) {
#pragma unroll
            for (int kt = 0; kt < 4; kt++) {
                uint32_t o = laddr + (uint32_t)(ng * 576 + kt * 8) * 4;
                uint32_t h0, h1, h2, h3, l0, l1, l2, l3;
                ldsm_x4(h0, h1, h2, h3, kh_b + o);
                ldsm_x4(l0, l1, l2, l3, kl_b + o);
                mma_bf16(sacc[2 * ng],     qh[kt][0], qh[kt][1], qh[kt][2], qh[kt][3], h0, h1);
                mma_bf16(sacc[2 * ng],     qh[kt][0], qh[kt][1], qh[kt][2], qh[kt][3], l0, l1);
                mma_bf16(sacc[2 * ng],     ql[kt][0], ql[kt][1], ql[kt][2], ql[kt][3], h0, h1);
                mma_bf16(sacc[2 * ng + 1], qh[kt][0], qh[kt][1], qh[kt][2], qh[kt][3], h2, h3);
                mma_bf16(sacc[2 * ng + 1], qh[kt][0], qh[kt][1], qh[kt][2], qh[kt][3], l2, l3);
                mma_bf16(sacc[2 * ng + 1], ql[kt][0], ql[kt][1], ql[kt][2], ql[kt][3], h2, h3);
            }
        }

        float m0 = -1e30f, m1 = -1e30f;
#pragma unroll
        for (int nt = 0; nt < 8; nt++) {
            m0 = fmaxf(m0, fmaxf(sacc[nt].x, sacc[nt].y));
            m1 = fmaxf(m1, fmaxf(sacc[nt].z, sacc[nt].w));
        }
#pragma unroll
        for (int o = 1; o <= 2; o <<= 1) {
            m0 = fmaxf(m0, __shfl_xor_sync(0xffffffffu, m0, o));
            m1 = fmaxf(m1, __shfl_xor_sync(0xffffffffu, m1, o));
        }
        float mn0 = fmaxf(mi0, m0), mn1 = fmaxf(mi1, m1);
        float corr0 = __expf(mi0 - mn0), corr1 = __expf(mi1 - mn1);
        float rs0 = 0.f, rs1 = 0.f;
#pragma unroll
        for (int nt = 0; nt < 8; nt++) {
            sacc[nt].x = __expf(sacc[nt].x - mn0);
            sacc[nt].y = __expf(sacc[nt].y - mn0);
            sacc[nt].z = __expf(sacc[nt].z - mn1);
            sacc[nt].w = __expf(sacc[nt].w - mn1);
            rs0 += sacc[nt].x + sacc[nt].y;
            rs1 += sacc[nt].z + sacc[nt].w;
        }
#pragma unroll
        for (int o = 1; o <= 2; o <<= 1) {
            rs0 += __shfl_xor_sync(0xffffffffu, rs0, o);
            rs1 += __shfl_xor_sync(0xffffffffu, rs1, o);
        }
        li0 = li0 * corr0 + rs0;
        li1 = li1 * corr1 + rs1;
        mi0 = mn0; mi1 = mn1;
#pragma unroll
        for (int j = 0; j < 8; j++) {
            oacc[j].x *= corr0; oacc[j].y *= corr0;
            oacc[j].z *= corr1; oacc[j].w *= corr1;
        }

        uint32_t ph[4][4], pl[4][4];
#pragma unroll
        for (int t = 0; t < 4; t++) {
            split2(sacc[2 * t].x,     sacc[2 * t].y,     ph[t][0], pl[t][0]);
            split2(sacc[2 * t].z,     sacc[2 * t].w,     ph[t][1], pl[t][1]);
            split2(sacc[2 * t + 1].x, sacc[2 * t + 1].y, ph[t][2], pl[t][2]);
            split2(sacc[2 * t + 1].z, sacc[2 * t + 1].w, ph[t][3], pl[t][3]);
        }

#pragma unroll
        for (int jg = 0; jg < 4; jg++) {
#pragma unroll
            for (int kt = 0; kt < 4; kt++) {
                uint32_t o = laddr + (uint32_t)(jg * 576 + kt * 8) * 4;
                uint32_t h0, h1, h2, h3, l0, l1, l2, l3;
                ldsm_x4(h0, h1, h2, h3, vh_b + o);
                ldsm_x4(l0, l1, l2, l3, vl_b + o);
                mma_bf16(oacc[2 * jg],     ph[kt][0], ph[kt][1], ph[kt][2], ph[kt][3], h0, h1);
                mma_bf16(oacc[2 * jg],     ph[kt][0], ph[kt][1], ph[kt][2], ph[kt][3], l0, l1);
                mma_bf16(oacc[2 * jg],     pl[kt][0], pl[kt][1], pl[kt][2], pl[kt][3], h0, h1);
                mma_bf16(oacc[2 * jg + 1], ph[kt][0], ph[kt][1], ph[kt][2], ph[kt][3], h2, h3);
                mma_bf16(oacc[2 * jg + 1], ph[kt][0], ph[kt][1], ph[kt][2], ph[kt][3], l2, l3);
                mma_bf16(oacc[2 * jg + 1], pl[kt][0], pl[kt][1], pl[kt][2], pl[kt][3], h2, h3);
            }
        }
        __syncthreads();
    }

    // normalize + split + write planes
    float inv0 = 1.f / li0, inv1 = 1.f / li1;
    const size_t row0 = ((size_t)b * S_ + q0 + r) * 512;
    const size_t row1 = row0 + 8 * 512;
#pragma unroll
    for (int j = 0; j < 8; j++) {
        int w = h * 32 + j * 4 + c;   // u32 word index within the 512-word row
        uint32_t hw, lw;
        split2(oacc[j].x * inv0, oacc[j].y * inv0, hw, lw);
        AOh[row0 + w] = hw; AOl[row0 + w] = lw;
        split2(oacc[j].z * inv1, oacc[j].w * inv1, hw, lw);
        AOh[row1 + w] = hw; AOl[row1 + w] = lw;
    }
}

// ---------------------------------------------------------------------------
extern "C" void kernel_launch(void* const* d_in, const int* in_sizes, int n_in,
                              void* d_out, int out_size)
{
    const float* queries = (const float*)d_in[0];
    const float* keys    = (const float*)d_in[1];
    const float* values  = (const float*)d_in[2];
    const float* W_q = (const float*)d_in[3];
    const float* b_q = (const float*)d_in[4];
    const float* W_k = (const float*)d_in[5];
    const float* b_k = (const float*)d_in[6];
    const float* W_v = (const float*)d_in[7];
    const float* b_v = (const float*)d_in[8];
    const float* W_o = (const float*)d_in[9];
    const float* b_o = (const float*)d_in[10];
    float* out = (float*)d_out;

    uint32_t *Qh, *Ql, *Kh, *Kl, *Vh, *Vl, *AOh, *AOl, *Xh, *Xl, *Wh, *Wl;
    cudaGetSymbolAddress((void**)&Qh, g_Qh);
    cudaGetSymbolAddress((void**)&Ql, g_Ql);
    cudaGetSymbolAddress((void**)&Kh, g_Kh);
    cudaGetSymbolAddress((void**)&Kl, g_Kl);
    cudaGetSymbolAddress((void**)&Vh, g_Vh);
    cudaGetSymbolAddress((void**)&Vl, g_Vl);
    cudaGetSymbolAddress((void**)&AOh, g_AOh);
    cudaGetSymbolAddress((void**)&AOl, g_AOl);
    cudaGetSymbolAddress((void**)&Xh, g_Xh);
    cudaGetSymbolAddress((void**)&Xl, g_Xl);
    cudaGetSymbolAddress((void**)&Wh, g_Wh);
    cudaGetSymbolAddress((void**)&Wl, g_Wl);

    const int M = B_ * S_;
    dim3 ggrid(D_ / 64, M / 128);
    const int gsmem = 2 * STG_U32 * 4;  // 61440
    cudaFuncSetAttribute(gemm_planes<0>, cudaFuncAttributeMaxDynamicSharedMemorySize, gsmem);
    cudaFuncSetAttribute(gemm_planes<1>, cudaFuncAttributeMaxDynamicSharedMemorySize, gsmem);
    cudaFuncSetAttribute(gemm_planes<2>, cudaFuncAttributeMaxDynamicSharedMemorySize, gsmem);
    cudaFuncSetAttribute(gemm_planes<3>, cudaFuncAttributeMaxDynamicSharedMemorySize, gsmem);

    const int nX4 = NE_ / 4;          // activation float4 count
    const int nW4 = D_ * D_ / 4;      // weight float4 count

    // Q projection
    split_kernel<<<nX4 / 256, 256>>>(queries, Xh, Xl, nX4);
    split_kernel<<<nW4 / 256, 256>>>(W_q, Wh, Wl, nW4);
    gemm_planes<1><<<ggrid, 256, gsmem>>>(Xh, Xl, Wh, Wl, b_q, nullptr, Qh, Ql, M, D_, D_);
    // K projection
    split_kernel<<<nX4 / 256, 256>>>(keys, Xh, Xl, nX4);
    split_kernel<<<nW4 / 256, 256>>>(W_k, Wh, Wl, nW4);
    gemm_planes<2><<<ggrid, 256, gsmem>>>(Xh, Xl, Wh, Wl, b_k, nullptr, Kh, Kl, M, D_, D_);
    // V projection (transposed planes)
    split_kernel<<<nX4 / 256, 256>>>(values, Xh, Xl, nX4);
    split_kernel<<<nW4 / 256, 256>>>(W_v, Wh, Wl, nW4);
    gemm_planes<3><<<ggrid, 256, gsmem>>>(Xh, Xl, Wh, Wl, b_v, nullptr, Vh, Vl, M, D_, D_);

    // attention
    const int asmem = 2 * 4 * 64 * 36 * 4;  // 73728
    cudaFuncSetAttribute(attn_mma, cudaFuncAttributeMaxDynamicSharedMemorySize, asmem);
    dim3 agrid(S_ / 128, H_, B_);
    attn_mma<<<agrid, 256, asmem>>>(Qh, Ql, Kh, Kl, Vh, Vl, AOh, AOl);

    // O projection
    split_kernel<<<nW4 / 256, 256>>>(W_o, Wh, Wl, nW4);
    gemm_planes<0><<<ggrid, 256, gsmem>>>(AOh, AOl, Wh, Wl, b_o, out, nullptr, nullptr, M, D_, D_);
}

// round 6
// speedup vs baseline: 5.0731x; 1.0883x over previous
#include <cuda_runtime.h>
#include <cuda_bf16.h>
#include <stdint.h>

#define B_  2
#define S_  2048
#define D_  1024
#define H_  16
#define DH_ 64
#define NE_ (B_ * S_ * D_)
#define NKB (S_ / 64)

// Scratch (allocation-free): bf16 hi/lo planes packed 2-per-u32.
__device__ uint32_t g_Qh[NE_ / 2], g_Ql[NE_ / 2];   // proj Q, pre-scaled 1/8
__device__ uint32_t g_Kh[NE_ / 2], g_Kl[NE_ / 2];   // proj K
__device__ uint32_t g_Vh[NE_ / 2], g_Vl[NE_ / 2];   // proj V transposed [b][h][dh][s]
__device__ uint32_t g_AOh[NE_ / 2], g_AOl[NE_ / 2]; // attention output planes
__device__ uint32_t g_Xh[NE_ / 2], g_Xl[NE_ / 2];   // split activation (reused)
__device__ uint32_t g_Wh[D_ * D_ / 2], g_Wl[D_ * D_ / 2]; // split weight (reused)

// ---------------------------------------------------------------------------
__device__ __forceinline__ void split2(float x, float y, uint32_t& hi, uint32_t& lo)
{
    __nv_bfloat162 h = __floats2bfloat162_rn(x, y);
    float rx = x - __bfloat162float(h.x);
    float ry = y - __bfloat162float(h.y);
    __nv_bfloat162 l = __floats2bfloat162_rn(rx, ry);
    hi = *reinterpret_cast<uint32_t*>(&h);
    lo = *reinterpret_cast<uint32_t*>(&l);
}

__device__ __forceinline__ void mma_bf16(float4& d,
    uint32_t a0, uint32_t a1, uint32_t a2, uint32_t a3,
    uint32_t b0, uint32_t b1)
{
    asm volatile(
        "mma.sync.aligned.m16n8k16.row.col.f32.bf16.bf16.f32 "
        "{%0,%1,%2,%3},{%4,%5,%6,%7},{%8,%9},{%0,%1,%2,%3};"
        : "+f"(d.x), "+f"(d.y), "+f"(d.z), "+f"(d.w)
        : "r"(a0), "r"(a1), "r"(a2), "r"(a3), "r"(b0), "r"(b1));
}

__device__ __forceinline__ void ldsm_x4(uint32_t& r0, uint32_t& r1,
                                        uint32_t& r2, uint32_t& r3, uint32_t addr)
{
    asm volatile("ldmatrix.sync.aligned.m8n8.x4.shared.b16 {%0,%1,%2,%3}, [%4];"
                 : "=r"(r0), "=r"(r1), "=r"(r2), "=r"(r3) : "r"(addr));
}

__device__ __forceinline__ void cp16(uint32_t smaddr, const void* g)
{
    asm volatile("cp.async.cg.shared.global [%0], [%1], 16;" :: "r"(smaddr), "l"(g));
}

// ---------------------------------------------------------------------------
// Split fp32 -> bf16 hi/lo planes.
// ---------------------------------------------------------------------------
__global__ __launch_bounds__(256) void split_kernel(
    const float* __restrict__ src, uint32_t* __restrict__ hi,
    uint32_t* __restrict__ lo, int n4)
{
    int i = blockIdx.x * 256 + threadIdx.x;
    if (i >= n4) return;
    float4 v = ((const float4*)src)[i];
    uint32_t h0, l0, h1, l1;
    split2(v.x, v.y, h0, l0);
    split2(v.z, v.w, h1, l1);
    ((uint2*)hi)[i] = make_uint2(h0, h1);
    ((uint2*)lo)[i] = make_uint2(l0, l1);
}

// ---------------------------------------------------------------------------
// bf16x3 GEMM from planes: C[M,N] = A @ W^T + bias.
// BM=128, BN=128, BK=32, 256 thr, 8 warps (4m x 2n), warp tile 32x64.
// MODE 0: fp32 C; 1: Q planes (x0.125); 2: planes; 3: planes transposed.
// Dyn smem: 2 stages x 10240 u32 = 81920 B.
// ---------------------------------------------------------------------------
#define GSTG   10240u
#define GA_LO  2560u
#define GW_HI  5120u
#define GW_LO  7680u

template <int MODE>
__global__ __launch_bounds__(256, 2) void gemm_planes(
    const uint32_t* __restrict__ Ah, const uint32_t* __restrict__ Al,
    const uint32_t* __restrict__ Wh, const uint32_t* __restrict__ Wl,
    const float* __restrict__ bias,
    float* __restrict__ Cf, uint32_t* __restrict__ Ch, uint32_t* __restrict__ Cl,
    int M, int N, int K)
{
    extern __shared__ uint32_t sg[];
    const uint32_t sb = (uint32_t)__cvta_generic_to_shared(sg);

    const int tid  = threadIdx.x;
    const int lane = tid & 31;
    const int wid  = tid >> 5;
    const int wm   = wid & 3;
    const int wn   = wid >> 2;
    const int r    = lane >> 2;
    const int c    = lane & 3;

    const int m_base = blockIdx.y * 128;
    const int n_base = blockIdx.x * 128;
    const int KW = K >> 1;

    const int lrA = (lane & 7) + (((lane >> 3) & 1) << 3);
    const int lcA = (lane >> 4) * 4;
    const int lrB = (lane & 7) + ((lane >> 4) << 3);
    const int lcB = ((lane >> 3) & 1) * 4;

    // loader: 512 cp16 per plane, 2 per thread per plane
    auto prefetch = [&](int ktile) {
        uint32_t base = sb + (uint32_t)(ktile & 1) * GSTG * 4u;
        int ktw = ktile * 16;
#pragma unroll
        for (int t = 0; t < 2; t++) {
            int idx = tid + t * 256;          // 0..511
            int row = idx >> 2, cg = (idx & 3) * 4;
            uint32_t so = (uint32_t)(row * 20 + cg) * 4u;
            size_t ga = (size_t)(m_base + row) * KW + ktw + cg;
            size_t gw = (size_t)(n_base + row) * KW + ktw + cg;
            cp16(base + so,                Ah + ga);
            cp16(base + GA_LO * 4u + so,   Al + ga);
            cp16(base + GW_HI * 4u + so,   Wh + gw);
            cp16(base + GW_LO * 4u + so,   Wl + gw);
        }
        asm volatile("cp.async.commit_group;" ::: "memory");
    };

    float4 acc[2][8];
#pragma unroll
    for (int i = 0; i < 2; i++)
#pragma unroll
        for (int j = 0; j < 8; j++) acc[i][j] = make_float4(0.f, 0.f, 0.f, 0.f);

    const int NT = K / 32;
    prefetch(0);

    for (int kt = 0; kt < NT; kt++) {
        if (kt + 1 < NT) {
            prefetch(kt + 1);
            asm volatile("cp.async.wait_group 1;" ::: "memory");
        } else {
            asm volatile("cp.async.wait_group 0;" ::: "memory");
        }
        __syncthreads();

        uint32_t base = sb + (uint32_t)(kt & 1) * GSTG * 4u;

#pragma unroll
        for (int ks = 0; ks < 2; ks++) {
            uint32_t ah[2][4], al[2][4];
#pragma unroll
            for (int mt = 0; mt < 2; mt++) {
                uint32_t o = (uint32_t)((wm * 32 + mt * 16 + lrA) * 20 + ks * 8 + lcA) * 4u;
                ldsm_x4(ah[mt][0], ah[mt][1], ah[mt][2], ah[mt][3], base + o);
                ldsm_x4(al[mt][0], al[mt][1], al[mt][2], al[mt][3], base + GA_LO * 4u + o);
            }
#pragma unroll
            for (int ntp = 0; ntp < 4; ntp++) {
                uint32_t o = (uint32_t)((wn * 64 + ntp * 16 + lrB) * 20 + ks * 8 + lcB) * 4u;
                uint32_t bh0, bh1, bh2, bh3, bl0, bl1, bl2, bl3;
                ldsm_x4(bh0, bh1, bh2, bh3, base + GW_HI * 4u + o);
                ldsm_x4(bl0, bl1, bl2, bl3, base + GW_LO * 4u + o);
#pragma unroll
                for (int mt = 0; mt < 2; mt++) {
                    mma_bf16(acc[mt][2 * ntp],     ah[mt][0], ah[mt][1], ah[mt][2], ah[mt][3], bh0, bh1);
                    mma_bf16(acc[mt][2 * ntp],     ah[mt][0], ah[mt][1], ah[mt][2], ah[mt][3], bl0, bl1);
                    mma_bf16(acc[mt][2 * ntp],     al[mt][0], al[mt][1], al[mt][2], al[mt][3], bh0, bh1);
                    mma_bf16(acc[mt][2 * ntp + 1], ah[mt][0], ah[mt][1], ah[mt][2], ah[mt][3], bh2, bh3);
                    mma_bf16(acc[mt][2 * ntp + 1], ah[mt][0], ah[mt][1], ah[mt][2], ah[mt][3], bl2, bl3);
                    mma_bf16(acc[mt][2 * ntp + 1], al[mt][0], al[mt][1], al[mt][2], al[mt][3], bh2, bh3);
                }
            }
        }
        __syncthreads();
    }

    // epilogue
#pragma unroll
    for (int mt = 0; mt < 2; mt++) {
#pragma unroll
        for (int nt = 0; nt < 8; nt++) {
            int gm0 = m_base + wm * 32 + mt * 16 + r;
            int gm1 = gm0 + 8;
            int gn  = n_base + wn * 64 + nt * 8 + c * 2;
            float b0v = bias[gn], b1v = bias[gn + 1];
            float f00 = acc[mt][nt].x + b0v, f01 = acc[mt][nt].y + b1v;
            float f10 = acc[mt][nt].z + b0v, f11 = acc[mt][nt].w + b1v;
            if (MODE == 1) { f00 *= 0.125f; f01 *= 0.125f; f10 *= 0.125f; f11 *= 0.125f; }

            if (MODE == 0) {
                *(float2*)(Cf + (size_t)gm0 * N + gn) = make_float2(f00, f01);
                *(float2*)(Cf + (size_t)gm1 * N + gn) = make_float2(f10, f11);
            } else if (MODE == 1 || MODE == 2) {
                uint32_t h0, l0, h1, l1;
                split2(f00, f01, h0, l0);
                split2(f10, f11, h1, l1);
                Ch[(size_t)gm0 * (N / 2) + gn / 2] = h0;
                Cl[(size_t)gm0 * (N / 2) + gn / 2] = l0;
                Ch[(size_t)gm1 * (N / 2) + gn / 2] = h1;
                Cl[(size_t)gm1 * (N / 2) + gn / 2] = l1;
            } else {
                __nv_bfloat16* Chb = (__nv_bfloat16*)Ch;
                __nv_bfloat16* Clb = (__nv_bfloat16*)Cl;
                float fv[2][2] = {{f00, f01}, {f10, f11}};
                int gms[2] = {gm0, gm1};
#pragma unroll
                for (int i = 0; i < 2; i++)
#pragma unroll
                    for (int j = 0; j < 2; j++) {
                        int m = gms[i], n = gn + j;
                        int bb = m >> 11, s = m & 2047;
                        int hh = n >> 6, dh = n & 63;
                        size_t idx = (((size_t)(bb * H_ + hh) * DH_ + dh) * S_) + s;
                        __nv_bfloat16 hv = __float2bfloat16_rn(fv[i][j]);
                        float lvf = fv[i][j] - __bfloat162float(hv);
                        Chb[idx] = hv;
                        Clb[idx] = __float2bfloat16_rn(lvf);
                    }
            }
        }
    }
}

// ---------------------------------------------------------------------------
// Flash attention, mma bf16x3. 4 warps/CTA, 32 q-rows per warp (2 m16 tiles),
// K/V fragment LDSMs shared across both m-tiles. cp.async double buffer.
// Grid (S/128, H, B). Dyn smem: 2 x 4 planes x 64 x 36 u32 = 73728 B.
// ---------------------------------------------------------------------------
__global__ __launch_bounds__(128, 2) void attn_mma(
    const uint32_t* __restrict__ Qh, const uint32_t* __restrict__ Ql,
    const uint32_t* __restrict__ Kh, const uint32_t* __restrict__ Kl,
    const uint32_t* __restrict__ Vh, const uint32_t* __restrict__ Vl,
    uint32_t* __restrict__ AOh, uint32_t* __restrict__ AOl)
{
    extern __shared__ uint32_t smu[];
    const int tid  = threadIdx.x;
    const int lane = tid & 31;
    const int wid  = tid >> 5;          // 0..3
    const int r    = lane >> 2;
    const int c    = lane & 3;
    const int h    = blockIdx.y;
    const int b    = blockIdx.z;
    const int q0   = blockIdx.x * 128 + wid * 32;

    const size_t qk_base = ((size_t)b * S_ * D_ + h * DH_) / 2;
    const size_t v_base  = ((size_t)(b * H_ + h) * DH_ * S_) / 2;
    const uint32_t* Qh32 = Qh + qk_base;
    const uint32_t* Ql32 = Ql + qk_base;
    const uint32_t* Kh32 = Kh + qk_base;
    const uint32_t* Kl32 = Kl + qk_base;
    const uint32_t* Vh32 = Vh + v_base;
    const uint32_t* Vl32 = Vl + v_base;

    const uint32_t sbase = (uint32_t)__cvta_generic_to_shared(smu);
    const int lr  = (lane & 7) + ((lane >> 4) << 3);
    const int lc4 = ((lane >> 3) & 1) * 4;
    const uint32_t laddr = (uint32_t)(lr * 36 + lc4) * 4;

    // Q fragments: 2 m-tiles x 4 k-chunks x 4 regs, hi+lo
    uint32_t qh[2][4][4], ql[2][4][4];
#pragma unroll
    for (int mt = 0; mt < 2; mt++) {
        int rb = q0 + mt * 16;
#pragma unroll
        for (int kt = 0; kt < 4; kt++) {
            qh[mt][kt][0] = Qh32[(size_t)(rb + r) * 512 + kt * 8 + c];
            qh[mt][kt][1] = Qh32[(size_t)(rb + 8 + r) * 512 + kt * 8 + c];
            qh[mt][kt][2] = Qh32[(size_t)(rb + r) * 512 + kt * 8 + c + 4];
            qh[mt][kt][3] = Qh32[(size_t)(rb + 8 + r) * 512 + kt * 8 + c + 4];
            ql[mt][kt][0] = Ql32[(size_t)(rb + r) * 512 + kt * 8 + c];
            ql[mt][kt][1] = Ql32[(size_t)(rb + 8 + r) * 512 + kt * 8 + c];
            ql[mt][kt][2] = Ql32[(size_t)(rb + r) * 512 + kt * 8 + c + 4];
            ql[mt][kt][3] = Ql32[(size_t)(rb + 8 + r) * 512 + kt * 8 + c + 4];
        }
    }

    float4 oacc[2][8];
#pragma unroll
    for (int mt = 0; mt < 2; mt++)
#pragma unroll
        for (int j = 0; j < 8; j++) oacc[mt][j] = make_float4(0.f, 0.f, 0.f, 0.f);
    float mi[2][2], li[2][2];
#pragma unroll
    for (int mt = 0; mt < 2; mt++) { mi[mt][0] = mi[mt][1] = -1e30f; li[mt][0] = li[mt][1] = 0.f; }

    auto prefetch = [&](int kb) {
        uint32_t bufb = sbase + (uint32_t)(kb & 1) * 9216 * 4;
#pragma unroll
        for (int t = 0; t < 4; t++) {
            int i = tid + t * 128;
            int row = i >> 3, col = (i & 7) * 4;
            uint32_t off = (uint32_t)(row * 36 + col) * 4;
            size_t kg = (size_t)(kb * 64 + row) * 512 + col;
            size_t vg = (size_t)row * 1024 + kb * 32 + col;
            cp16(bufb + off,            Kh32 + kg);
            cp16(bufb + 2304 * 4 + off, Kl32 + kg);
            cp16(bufb + 4608 * 4 + off, Vh32 + vg);
            cp16(bufb + 6912 * 4 + off, Vl32 + vg);
        }
        asm volatile("cp.async.commit_group;" ::: "memory");
    };

    prefetch(0);

    for (int kb = 0; kb < NKB; kb++) {
        if (kb + 1 < NKB) {
            prefetch(kb + 1);
            asm volatile("cp.async.wait_group 1;" ::: "memory");
        } else {
            asm volatile("cp.async.wait_group 0;" ::: "memory");
        }
        __syncthreads();

        uint32_t bufb = sbase + (uint32_t)(kb & 1) * 9216 * 4;
        uint32_t kh_b = bufb, kl_b = bufb + 2304 * 4;
        uint32_t vh_b = bufb + 4608 * 4, vl_b = bufb + 6912 * 4;

        // ---- scores = Q @ K^T ----
        float4 sacc[2][8];
#pragma unroll
        for (int mt = 0; mt < 2; mt++)
#pragma unroll
            for (int nt = 0; nt < 8; nt++) sacc[mt][nt] = make_float4(0.f, 0.f, 0.f, 0.f);
#pragma unroll
        for (int ng = 0; ng < 4; ng++) {
#pragma unroll
            for (int kt = 0; kt < 4; kt++) {
                uint32_t o = laddr + (uint32_t)(ng * 576 + kt * 8) * 4;
                uint32_t h0, h1, h2, h3, l0, l1, l2, l3;
                ldsm_x4(h0, h1, h2, h3, kh_b + o);
                ldsm_x4(l0, l1, l2, l3, kl_b + o);
#pragma unroll
                for (int mt = 0; mt < 2; mt++) {
                    mma_bf16(sacc[mt][2 * ng],     qh[mt][kt][0], qh[mt][kt][1], qh[mt][kt][2], qh[mt][kt][3], h0, h1);
                    mma_bf16(sacc[mt][2 * ng],     qh[mt][kt][0], qh[mt][kt][1], qh[mt][kt][2], qh[mt][kt][3], l0, l1);
                    mma_bf16(sacc[mt][2 * ng],     ql[mt][kt][0], ql[mt][kt][1], ql[mt][kt][2], ql[mt][kt][3], h0, h1);
                    mma_bf16(sacc[mt][2 * ng + 1], qh[mt][kt][0], qh[mt][kt][1], qh[mt][kt][2], qh[mt][kt][3], h2, h3);
                    mma_bf16(sacc[mt][2 * ng + 1], qh[mt][kt][0], qh[mt][kt][1], qh[mt][kt][2], qh[mt][kt][3], l2, l3);
                    mma_bf16(sacc[mt][2 * ng + 1], ql[mt][kt][0], ql[mt][kt][1], ql[mt][kt][2], ql[mt][kt][3], h2, h3);
                }
            }
        }

        // ---- online softmax + P fragments + PV ----
        uint32_t ph[2][4][4], pl[2][4][4];
#pragma unroll
        for (int mt = 0; mt < 2; mt++) {
            float m0 = -1e30f, m1 = -1e30f;
#pragma unroll
            for (int nt = 0; nt < 8; nt++) {
                m0 = fmaxf(m0, fmaxf(sacc[mt][nt].x, sacc[mt][nt].y));
                m1 = fmaxf(m1, fmaxf(sacc[mt][nt].z, sacc[mt][nt].w));
            }
#pragma unroll
            for (int o = 1; o <= 2; o <<= 1) {
                m0 = fmaxf(m0, __shfl_xor_sync(0xffffffffu, m0, o));
                m1 = fmaxf(m1, __shfl_xor_sync(0xffffffffu, m1, o));
            }
            float mn0 = fmaxf(mi[mt][0], m0), mn1 = fmaxf(mi[mt][1], m1);
            float corr0 = __expf(mi[mt][0] - mn0), corr1 = __expf(mi[mt][1] - mn1);
            float rs0 = 0.f, rs1 = 0.f;
#pragma unroll
            for (int nt = 0; nt < 8; nt++) {
                sacc[mt][nt].x = __expf(sacc[mt][nt].x - mn0);
                sacc[mt][nt].y = __expf(sacc[mt][nt].y - mn0);
                sacc[mt][nt].z = __expf(sacc[mt][nt].z - mn1);
                sacc[mt][nt].w = __expf(sacc[mt][nt].w - mn1);
                rs0 += sacc[mt][nt].x + sacc[mt][nt].y;
                rs1 += sacc[mt][nt].z + sacc[mt][nt].w;
            }
#pragma unroll
            for (int o = 1; o <= 2; o <<= 1) {
                rs0 += __shfl_xor_sync(0xffffffffu, rs0, o);
                rs1 += __shfl_xor_sync(0xffffffffu, rs1, o);
            }
            li[mt][0] = li[mt][0] * corr0 + rs0;
            li[mt][1] = li[mt][1] * corr1 + rs1;
            mi[mt][0] = mn0; mi[mt][1] = mn1;
#pragma unroll
            for (int j = 0; j < 8; j++) {
                oacc[mt][j].x *= corr0; oacc[mt][j].y *= corr0;
                oacc[mt][j].z *= corr1; oacc[mt][j].w *= corr1;
            }
#pragma unroll
            for (int t = 0; t < 4; t++) {
                split2(sacc[mt][2 * t].x,     sacc[mt][2 * t].y,     ph[mt][t][0], pl[mt][t][0]);
                split2(sacc[mt][2 * t].z,     sacc[mt][2 * t].w,     ph[mt][t][1], pl[mt][t][1]);
                split2(sacc[mt][2 * t + 1].x, sacc[mt][2 * t + 1].y, ph[mt][t][2], pl[mt][t][2]);
                split2(sacc[mt][2 * t + 1].z, sacc[mt][2 * t + 1].w, ph[mt][t][3], pl[mt][t][3]);
            }
        }

        // ---- O += P @ V ----
#pragma unroll
        for (int jg = 0; jg < 4; jg++) {
#pragma unroll
            for (int kt = 0; kt < 4; kt++) {
                uint32_t o = laddr + (uint32_t)(jg * 576 + kt * 8) * 4;
                uint32_t h0, h1, h2, h3, l0, l1, l2, l3;
                ldsm_x4(h0, h1, h2, h3, vh_b + o);
                ldsm_x4(l0, l1, l2, l3, vl_b + o);
#pragma unroll
                for (int mt = 0; mt < 2; mt++) {
                    mma_bf16(oacc[mt][2 * jg],     ph[mt][kt][0], ph[mt][kt][1], ph[mt][kt][2], ph[mt][kt][3], h0, h1);
                    mma_bf16(oacc[mt][2 * jg],     ph[mt][kt][0], ph[mt][kt][1], ph[mt][kt][2], ph[mt][kt][3], l0, l1);
                    mma_bf16(oacc[mt][2 * jg],     pl[mt][kt][0], pl[mt][kt][1], pl[mt][kt][2], pl[mt][kt][3], h0, h1);
                    mma_bf16(oacc[mt][2 * jg + 1], ph[mt][kt][0], ph[mt][kt][1], ph[mt][kt][2], ph[mt][kt][3], h2, h3);
                    mma_bf16(oacc[mt][2 * jg + 1], ph[mt][kt][0], ph[mt][kt][1], ph[mt][kt][2], ph[mt][kt][3], l2, l3);
                    mma_bf16(oacc[mt][2 * jg + 1], pl[mt][kt][0], pl[mt][kt][1], pl[mt][kt][2], pl[mt][kt][3], h2, h3);
                }
            }
        }
        __syncthreads();
    }

    // ---- normalize + split + write planes ----
#pragma unroll
    for (int mt = 0; mt < 2; mt++) {
        float inv0 = 1.f / li[mt][0], inv1 = 1.f / li[mt][1];
        const size_t row0 = ((size_t)b * S_ + q0 + mt * 16 + r) * 512;
        const size_t row1 = row0 + 8 * 512;
#pragma unroll
        for (int j = 0; j < 8; j++) {
            int w = h * 32 + j * 4 + c;
            uint32_t hw, lw;
            split2(oacc[mt][j].x * inv0, oacc[mt][j].y * inv0, hw, lw);
            AOh[row0 + w] = hw; AOl[row0 + w] = lw;
            split2(oacc[mt][j].z * inv1, oacc[mt][j].w * inv1, hw, lw);
            AOh[row1 + w] = hw; AOl[row1 + w] = lw;
        }
    }
}

// ---------------------------------------------------------------------------
extern "C" void kernel_launch(void* const* d_in, const int* in_sizes, int n_in,
                              void* d_out, int out_size)
{
    const float* queries = (const float*)d_in[0];
    const float* keys    = (const float*)d_in[1];
    const float* values  = (const float*)d_in[2];
    const float* W_q = (const float*)d_in[3];
    const float* b_q = (const float*)d_in[4];
    const float* W_k = (const float*)d_in[5];
    const float* b_k = (const float*)d_in[6];
    const float* W_v = (const float*)d_in[7];
    const float* b_v = (const float*)d_in[8];
    const float* W_o = (const float*)d_in[9];
    const float* b_o = (const float*)d_in[10];
    float* out = (float*)d_out;

    uint32_t *Qh, *Ql, *Kh, *Kl, *Vh, *Vl, *AOh, *AOl, *Xh, *Xl, *Wh, *Wl;
    cudaGetSymbolAddress((void**)&Qh, g_Qh);
    cudaGetSymbolAddress((void**)&Ql, g_Ql);
    cudaGetSymbolAddress((void**)&Kh, g_Kh);
    cudaGetSymbolAddress((void**)&Kl, g_Kl);
    cudaGetSymbolAddress((void**)&Vh, g_Vh);
    cudaGetSymbolAddress((void**)&Vl, g_Vl);
    cudaGetSymbolAddress((void**)&AOh, g_AOh);
    cudaGetSymbolAddress((void**)&AOl, g_AOl);
    cudaGetSymbolAddress((void**)&Xh, g_Xh);
    cudaGetSymbolAddress((void**)&Xl, g_Xl);
    cudaGetSymbolAddress((void**)&Wh, g_Wh);
    cudaGetSymbolAddress((void**)&Wl, g_Wl);

    const int M = B_ * S_;
    dim3 ggrid(D_ / 128, M / 128);            // (8, 32)
    const int gsmem = 2 * GSTG * 4;           // 81920
    cudaFuncSetAttribute(gemm_planes<0>, cudaFuncAttributeMaxDynamicSharedMemorySize, gsmem);
    cudaFuncSetAttribute(gemm_planes<1>, cudaFuncAttributeMaxDynamicSharedMemorySize, gsmem);
    cudaFuncSetAttribute(gemm_planes<2>, cudaFuncAttributeMaxDynamicSharedMemorySize, gsmem);
    cudaFuncSetAttribute(gemm_planes<3>, cudaFuncAttributeMaxDynamicSharedMemorySize, gsmem);

    const int nX4 = NE_ / 4;
    const int nW4 = D_ * D_ / 4;

    // Q projection
    split_kernel<<<nX4 / 256, 256>>>(queries, Xh, Xl, nX4);
    split_kernel<<<nW4 / 256, 256>>>(W_q, Wh, Wl, nW4);
    gemm_planes<1><<<ggrid, 256, gsmem>>>(Xh, Xl, Wh, Wl, b_q, nullptr, Qh, Ql, M, D_, D_);
    // K projection
    split_kernel<<<nX4 / 256, 256>>>(keys, Xh, Xl, nX4);
    split_kernel<<<nW4 / 256, 256>>>(W_k, Wh, Wl, nW4);
    gemm_planes<2><<<ggrid, 256, gsmem>>>(Xh, Xl, Wh, Wl, b_k, nullptr, Kh, Kl, M, D_, D_);
    // V projection (transposed planes)
    split_kernel<<<nX4 / 256, 256>>>(values, Xh, Xl, nX4);
    split_kernel<<<nW4 / 256, 256>>>(W_v, Wh, Wl, nW4);
    gemm_planes<3><<<ggrid, 256, gsmem>>>(Xh, Xl, Wh, Wl, b_v, nullptr, Vh, Vl, M, D_, D_);

    // attention
    const int asmem = 2 * 4 * 64 * 36 * 4;    // 73728
    cudaFuncSetAttribute(attn_mma, cudaFuncAttributeMaxDynamicSharedMemorySize, asmem);
    dim3 agrid(S_ / 128, H_, B_);
    attn_mma<<<agrid, 128, asmem>>>(Qh, Ql, Kh, Kl, Vh, Vl, AOh, AOl);

    // O projection
    split_kernel<<<nW4 / 256, 256>>>(W_o, Wh, Wl, nW4);
    gemm_planes<0><<<ggrid, 256, gsmem>>>(AOh, AOl, Wh, Wl, b_o, out, nullptr, nullptr, M, D_, D_);
}

// round 7
// speedup vs baseline: 5.3346x; 1.0515x over previous
#include <cuda_runtime.h>
#include <cuda_bf16.h>
#include <stdint.h>

#define B_  2
#define S_  2048
#define D_  1024
#define H_  16
#define DH_ 64
#define NE_ (B_ * S_ * D_)
#define NKB (S_ / 64)
#define NW_ (D_ * D_)

// Scratch (allocation-free): bf16 hi/lo planes packed 2-per-u32.
__device__ uint32_t g_Qh[NE_ / 2], g_Ql[NE_ / 2];   // proj Q, pre-scaled
__device__ uint32_t g_Kh[NE_ / 2], g_Kl[NE_ / 2];   // proj K
__device__ uint32_t g_Vh[NE_ / 2], g_Vl[NE_ / 2];   // proj V transposed [b][h][dh][s]
__device__ uint32_t g_AOh[NE_ / 2], g_AOl[NE_ / 2]; // attention output planes
__device__ uint32_t g_Xqh[NE_ / 2], g_Xql[NE_ / 2]; // split queries
__device__ uint32_t g_Xkh[NE_ / 2], g_Xkl[NE_ / 2]; // split keys
__device__ uint32_t g_Xvh[NE_ / 2], g_Xvl[NE_ / 2]; // split values
__device__ uint32_t g_Wqh[NW_ / 2], g_Wql[NW_ / 2];
__device__ uint32_t g_Wkh[NW_ / 2], g_Wkl[NW_ / 2];
__device__ uint32_t g_Wvh[NW_ / 2], g_Wvl[NW_ / 2];
__device__ uint32_t g_Woh[NW_ / 2], g_Wol[NW_ / 2];

// scale for Q projection output: (1/8) * log2(e)  [folds exp->exp2]
#define QSCALE 0.1803368801111204f

// ---------------------------------------------------------------------------
__device__ __forceinline__ void split2(float x, float y, uint32_t& hi, uint32_t& lo)
{
    __nv_bfloat162 h = __floats2bfloat162_rn(x, y);
    float rx = x - __bfloat162float(h.x);
    float ry = y - __bfloat162float(h.y);
    __nv_bfloat162 l = __floats2bfloat162_rn(rx, ry);
    hi = *reinterpret_cast<uint32_t*>(&h);
    lo = *reinterpret_cast<uint32_t*>(&l);
}

__device__ __forceinline__ void mma_bf16(float4& d,
    uint32_t a0, uint32_t a1, uint32_t a2, uint32_t a3,
    uint32_t b0, uint32_t b1)
{
    asm volatile(
        "mma.sync.aligned.m16n8k16.row.col.f32.bf16.bf16.f32 "
        "{%0,%1,%2,%3},{%4,%5,%6,%7},{%8,%9},{%0,%1,%2,%3};"
        : "+f"(d.x), "+f"(d.y), "+f"(d.z), "+f"(d.w)
        : "r"(a0), "r"(a1), "r"(a2), "r"(a3), "r"(b0), "r"(b1));
}

__device__ __forceinline__ void ldsm_x4(uint32_t& r0, uint32_t& r1,
                                        uint32_t& r2, uint32_t& r3, uint32_t addr)
{
    asm volatile("ldmatrix.sync.aligned.m8n8.x4.shared.b16 {%0,%1,%2,%3}, [%4];"
                 : "=r"(r0), "=r"(r1), "=r"(r2), "=r"(r3) : "r"(addr));
}

__device__ __forceinline__ void cp16(uint32_t smaddr, const void* g)
{
    asm volatile("cp.async.cg.shared.global [%0], [%1], 16;" :: "r"(smaddr), "l"(g));
}

// ---------------------------------------------------------------------------
// ONE fused split pass: 3 activations (4096 blocks each) + 4 weights (1024 each).
// ---------------------------------------------------------------------------
__global__ __launch_bounds__(256) void split_all(
    const float* __restrict__ q, const float* __restrict__ k, const float* __restrict__ v,
    const float* __restrict__ wq, const float* __restrict__ wk,
    const float* __restrict__ wv, const float* __restrict__ wo)
{
    const int bid = blockIdx.x;
    const float* src;
    uint32_t *hi, *lo;
    int i;
    if (bid < 12288) {
        int seg = bid >> 12;
        i = (bid & 4095) * 256 + threadIdx.x;
        if (seg == 0)      { src = q; hi = g_Xqh; lo = g_Xql; }
        else if (seg == 1) { src = k; hi = g_Xkh; lo = g_Xkl; }
        else               { src = v; hi = g_Xvh; lo = g_Xvl; }
    } else {
        int seg = (bid - 12288) >> 10;
        i = ((bid - 12288) & 1023) * 256 + threadIdx.x;
        if (seg == 0)      { src = wq; hi = g_Wqh; lo = g_Wql; }
        else if (seg == 1) { src = wk; hi = g_Wkh; lo = g_Wkl; }
        else if (seg == 2) { src = wv; hi = g_Wvh; lo = g_Wvl; }
        else               { src = wo; hi = g_Woh; lo = g_Wol; }
    }
    float4 val = ((const float4*)src)[i];
    uint32_t h0, l0, h1, l1;
    split2(val.x, val.y, h0, l0);
    split2(val.z, val.w, h1, l1);
    ((uint2*)hi)[i] = make_uint2(h0, h1);
    ((uint2*)lo)[i] = make_uint2(l0, l1);
}

// ---------------------------------------------------------------------------
// bf16x3 GEMM core (BM=128, BN=128, BK=32, 256 thr, warp tile 32x64).
// mode 0: fp32 out; 1: Q planes (xQSCALE); 2: planes; 3: planes transposed.
// ---------------------------------------------------------------------------
#define GSTG   10240u
#define GA_LO  2560u
#define GW_HI  5120u
#define GW_LO  7680u

__device__ __forceinline__ void gemm_core(
    const uint32_t* __restrict__ Ah, const uint32_t* __restrict__ Al,
    const uint32_t* __restrict__ Wh, const uint32_t* __restrict__ Wl,
    const float* __restrict__ bias,
    float* __restrict__ Cf, uint32_t* __restrict__ Ch, uint32_t* __restrict__ Cl,
    int mode, uint32_t sb)
{
    const int tid  = threadIdx.x;
    const int lane = tid & 31;
    const int wid  = tid >> 5;
    const int wm   = wid & 3;
    const int wn   = wid >> 2;
    const int r    = lane >> 2;
    const int c    = lane & 3;

    const int m_base = blockIdx.y * 128;
    const int n_base = blockIdx.x * 128;
    const int KW = D_ >> 1;

    const int lrA = (lane & 7) + (((lane >> 3) & 1) << 3);
    const int lcA = (lane >> 4) * 4;
    const int lrB = (lane & 7) + ((lane >> 4) << 3);
    const int lcB = ((lane >> 3) & 1) * 4;

    auto prefetch = [&](int ktile) {
        uint32_t base = sb + (uint32_t)(ktile & 1) * GSTG * 4u;
        int ktw = ktile * 16;
#pragma unroll
        for (int t = 0; t < 2; t++) {
            int idx = tid + t * 256;
            int row = idx >> 2, cg = (idx & 3) * 4;
            uint32_t so = (uint32_t)(row * 20 + cg) * 4u;
            size_t ga = (size_t)(m_base + row) * KW + ktw + cg;
            size_t gw = (size_t)(n_base + row) * KW + ktw + cg;
            cp16(base + so,                Ah + ga);
            cp16(base + GA_LO * 4u + so,   Al + ga);
            cp16(base + GW_HI * 4u + so,   Wh + gw);
            cp16(base + GW_LO * 4u + so,   Wl + gw);
        }
        asm volatile("cp.async.commit_group;" ::: "memory");
    };

    float4 acc[2][8];
#pragma unroll
    for (int i = 0; i < 2; i++)
#pragma unroll
        for (int j = 0; j < 8; j++) acc[i][j] = make_float4(0.f, 0.f, 0.f, 0.f);

    const int NT = D_ / 32;
    prefetch(0);

    for (int kt = 0; kt < NT; kt++) {
        if (kt + 1 < NT) {
            prefetch(kt + 1);
            asm volatile("cp.async.wait_group 1;" ::: "memory");
        } else {
            asm volatile("cp.async.wait_group 0;" ::: "memory");
        }
        __syncthreads();

        uint32_t base = sb + (uint32_t)(kt & 1) * GSTG * 4u;

#pragma unroll
        for (int ks = 0; ks < 2; ks++) {
            uint32_t ah[2][4], al[2][4];
#pragma unroll
            for (int mt = 0; mt < 2; mt++) {
                uint32_t o = (uint32_t)((wm * 32 + mt * 16 + lrA) * 20 + ks * 8 + lcA) * 4u;
                ldsm_x4(ah[mt][0], ah[mt][1], ah[mt][2], ah[mt][3], base + o);
                ldsm_x4(al[mt][0], al[mt][1], al[mt][2], al[mt][3], base + GA_LO * 4u + o);
            }
#pragma unroll
            for (int ntp = 0; ntp < 4; ntp++) {
                uint32_t o = (uint32_t)((wn * 64 + ntp * 16 + lrB) * 20 + ks * 8 + lcB) * 4u;
                uint32_t bh0, bh1, bh2, bh3, bl0, bl1, bl2, bl3;
                ldsm_x4(bh0, bh1, bh2, bh3, base + GW_HI * 4u + o);
                ldsm_x4(bl0, bl1, bl2, bl3, base + GW_LO * 4u + o);
#pragma unroll
                for (int mt = 0; mt < 2; mt++) {
                    mma_bf16(acc[mt][2 * ntp],     ah[mt][0], ah[mt][1], ah[mt][2], ah[mt][3], bh0, bh1);
                    mma_bf16(acc[mt][2 * ntp],     ah[mt][0], ah[mt][1], ah[mt][2], ah[mt][3], bl0, bl1);
                    mma_bf16(acc[mt][2 * ntp],     al[mt][0], al[mt][1], al[mt][2], al[mt][3], bh0, bh1);
                    mma_bf16(acc[mt][2 * ntp + 1], ah[mt][0], ah[mt][1], ah[mt][2], ah[mt][3], bh2, bh3);
                    mma_bf16(acc[mt][2 * ntp + 1], ah[mt][0], ah[mt][1], ah[mt][2], ah[mt][3], bl2, bl3);
                    mma_bf16(acc[mt][2 * ntp + 1], al[mt][0], al[mt][1], al[mt][2], al[mt][3], bh2, bh3);
                }
            }
        }
        __syncthreads();
    }

    // epilogue
#pragma unroll
    for (int mt = 0; mt < 2; mt++) {
#pragma unroll
        for (int nt = 0; nt < 8; nt++) {
            int gm0 = m_base + wm * 32 + mt * 16 + r;
            int gm1 = gm0 + 8;
            int gn  = n_base + wn * 64 + nt * 8 + c * 2;
            float b0v = bias[gn], b1v = bias[gn + 1];
            float f00 = acc[mt][nt].x + b0v, f01 = acc[mt][nt].y + b1v;
            float f10 = acc[mt][nt].z + b0v, f11 = acc[mt][nt].w + b1v;
            if (mode == 1) { f00 *= QSCALE; f01 *= QSCALE; f10 *= QSCALE; f11 *= QSCALE; }

            if (mode == 0) {
                *(float2*)(Cf + (size_t)gm0 * D_ + gn) = make_float2(f00, f01);
                *(float2*)(Cf + (size_t)gm1 * D_ + gn) = make_float2(f10, f11);
            } else if (mode == 1 || mode == 2) {
                uint32_t h0, l0, h1, l1;
                split2(f00, f01, h0, l0);
                split2(f10, f11, h1, l1);
                Ch[(size_t)gm0 * 512 + gn / 2] = h0;
                Cl[(size_t)gm0 * 512 + gn / 2] = l0;
                Ch[(size_t)gm1 * 512 + gn / 2] = h1;
                Cl[(size_t)gm1 * 512 + gn / 2] = l1;
            } else {
                __nv_bfloat16* Chb = (__nv_bfloat16*)Ch;
                __nv_bfloat16* Clb = (__nv_bfloat16*)Cl;
                float fv[2][2] = {{f00, f01}, {f10, f11}};
                int gms[2] = {gm0, gm1};
#pragma unroll
                for (int i = 0; i < 2; i++)
#pragma unroll
                    for (int j = 0; j < 2; j++) {
                        int m = gms[i], n = gn + j;
                        int bb = m >> 11, s = m & 2047;
                        int hh = n >> 6, dh = n & 63;
                        size_t idx = (((size_t)(bb * H_ + hh) * DH_ + dh) * S_) + s;
                        __nv_bfloat16 hv = __float2bfloat16_rn(fv[i][j]);
                        float lvf = fv[i][j] - __bfloat162float(hv);
                        Chb[idx] = hv;
                        Clb[idx] = __float2bfloat16_rn(lvf);
                    }
            }
        }
    }
}

// Fused Q/K/V projections: grid.z picks the GEMM.
__global__ __launch_bounds__(256, 2) void gemm_qkv(
    const float* __restrict__ b_q, const float* __restrict__ b_k,
    const float* __restrict__ b_v)
{
    extern __shared__ uint32_t sg[];
    const uint32_t sb = (uint32_t)__cvta_generic_to_shared(sg);
    const int z = blockIdx.z;
    if (z == 0)
        gemm_core(g_Xqh, g_Xql, g_Wqh, g_Wql, b_q, nullptr, g_Qh, g_Ql, 1, sb);
    else if (z == 1)
        gemm_core(g_Xkh, g_Xkl, g_Wkh, g_Wkl, b_k, nullptr, g_Kh, g_Kl, 2, sb);
    else
        gemm_core(g_Xvh, g_Xvl, g_Wvh, g_Wvl, b_v, nullptr, g_Vh, g_Vl, 3, sb);
}

// O projection
__global__ __launch_bounds__(256, 2) void gemm_out(
    const float* __restrict__ b_o, float* __restrict__ out)
{
    extern __shared__ uint32_t sg[];
    const uint32_t sb = (uint32_t)__cvta_generic_to_shared(sg);
    gemm_core(g_AOh, g_AOl, g_Woh, g_Wol, b_o, out, nullptr, nullptr, 0, sb);
}

// ---------------------------------------------------------------------------
// Flash attention, mma bf16x3 (scores in log2 units; exp2f softmax).
// 4 warps/CTA, 32 q-rows per warp, cp.async double buffer.
// ---------------------------------------------------------------------------
__global__ __launch_bounds__(128, 2) void attn_mma(
    const uint32_t* __restrict__ Qh, const uint32_t* __restrict__ Ql,
    const uint32_t* __restrict__ Kh, const uint32_t* __restrict__ Kl,
    const uint32_t* __restrict__ Vh, const uint32_t* __restrict__ Vl,
    uint32_t* __restrict__ AOh, uint32_t* __restrict__ AOl)
{
    extern __shared__ uint32_t smu[];
    const int tid  = threadIdx.x;
    const int lane = tid & 31;
    const int wid  = tid >> 5;
    const int r    = lane >> 2;
    const int c    = lane & 3;
    const int h    = blockIdx.y;
    const int b    = blockIdx.z;
    const int q0   = blockIdx.x * 128 + wid * 32;

    const size_t qk_base = ((size_t)b * S_ * D_ + h * DH_) / 2;
    const size_t v_base  = ((size_t)(b * H_ + h) * DH_ * S_) / 2;
    const uint32_t* Qh32 = Qh + qk_base;
    const uint32_t* Ql32 = Ql + qk_base;
    const uint32_t* Kh32 = Kh + qk_base;
    const uint32_t* Kl32 = Kl + qk_base;
    const uint32_t* Vh32 = Vh + v_base;
    const uint32_t* Vl32 = Vl + v_base;

    const uint32_t sbase = (uint32_t)__cvta_generic_to_shared(smu);
    const int lr  = (lane & 7) + ((lane >> 4) << 3);
    const int lc4 = ((lane >> 3) & 1) * 4;
    const uint32_t laddr = (uint32_t)(lr * 36 + lc4) * 4;

    uint32_t qh[2][4][4], ql[2][4][4];
#pragma unroll
    for (int mt = 0; mt < 2; mt++) {
        int rb = q0 + mt * 16;
#pragma unroll
        for (int kt = 0; kt < 4; kt++) {
            qh[mt][kt][0] = Qh32[(size_t)(rb + r) * 512 + kt * 8 + c];
            qh[mt][kt][1] = Qh32[(size_t)(rb + 8 + r) * 512 + kt * 8 + c];
            qh[mt][kt][2] = Qh32[(size_t)(rb + r) * 512 + kt * 8 + c + 4];
            qh[mt][kt][3] = Qh32[(size_t)(rb + 8 + r) * 512 + kt * 8 + c + 4];
            ql[mt][kt][0] = Ql32[(size_t)(rb + r) * 512 + kt * 8 + c];
            ql[mt][kt][1] = Ql32[(size_t)(rb + 8 + r) * 512 + kt * 8 + c];
            ql[mt][kt][2] = Ql32[(size_t)(rb + r) * 512 + kt * 8 + c + 4];
            ql[mt][kt][3] = Ql32[(size_t)(rb + 8 + r) * 512 + kt * 8 + c + 4];
        }
    }

    float4 oacc[2][8];
#pragma unroll
    for (int mt = 0; mt < 2; mt++)
#pragma unroll
        for (int j = 0; j < 8; j++) oacc[mt][j] = make_float4(0.f, 0.f, 0.f, 0.f);
    float mi[2][2], li[2][2];
#pragma unroll
    for (int mt = 0; mt < 2; mt++) { mi[mt][0] = mi[mt][1] = -1e30f; li[mt][0] = li[mt][1] = 0.f; }

    auto prefetch = [&](int kb) {
        uint32_t bufb = sbase + (uint32_t)(kb & 1) * 9216 * 4;
#pragma unroll
        for (int t = 0; t < 4; t++) {
            int i = tid + t * 128;
            int row = i >> 3, col = (i & 7) * 4;
            uint32_t off = (uint32_t)(row * 36 + col) * 4;
            size_t kg = (size_t)(kb * 64 + row) * 512 + col;
            size_t vg = (size_t)row * 1024 + kb * 32 + col;
            cp16(bufb + off,            Kh32 + kg);
            cp16(bufb + 2304 * 4 + off, Kl32 + kg);
            cp16(bufb + 4608 * 4 + off, Vh32 + vg);
            cp16(bufb + 6912 * 4 + off, Vl32 + vg);
        }
        asm volatile("cp.async.commit_group;" ::: "memory");
    };

    prefetch(0);

    for (int kb = 0; kb < NKB; kb++) {
        if (kb + 1 < NKB) {
            prefetch(kb + 1);
            asm volatile("cp.async.wait_group 1;" ::: "memory");
        } else {
            asm volatile("cp.async.wait_group 0;" ::: "memory");
        }
        __syncthreads();

        uint32_t bufb = sbase + (uint32_t)(kb & 1) * 9216 * 4;
        uint32_t kh_b = bufb, kl_b = bufb + 2304 * 4;
        uint32_t vh_b = bufb + 4608 * 4, vl_b = bufb + 6912 * 4;

        float4 sacc[2][8];
#pragma unroll
        for (int mt = 0; mt < 2; mt++)
#pragma unroll
            for (int nt = 0; nt < 8; nt++) sacc[mt][nt] = make_float4(0.f, 0.f, 0.f, 0.f);
#pragma unroll
        for (int ng = 0; ng < 4; ng++) {
#pragma unroll
            for (int kt = 0; kt < 4; kt++) {
                uint32_t o = laddr + (uint32_t)(ng * 576 + kt * 8) * 4;
                uint32_t h0, h1, h2, h3, l0, l1, l2, l3;
                ldsm_x4(h0, h1, h2, h3, kh_b + o);
                ldsm_x4(l0, l1, l2, l3, kl_b + o);
#pragma unroll
                for (int mt = 0; mt < 2; mt++) {
                    mma_bf16(sacc[mt][2 * ng],     qh[mt][kt][0], qh[mt][kt][1], qh[mt][kt][2], qh[mt][kt][3], h0, h1);
                    mma_bf16(sacc[mt][2 * ng],     qh[mt][kt][0], qh[mt][kt][1], qh[mt][kt][2], qh[mt][kt][3], l0, l1);
                    mma_bf16(sacc[mt][2 * ng],     ql[mt][kt][0], ql[mt][kt][1], ql[mt][kt][2], ql[mt][kt][3], h0, h1);
                    mma_bf16(sacc[mt][2 * ng + 1], qh[mt][kt][0], qh[mt][kt][1], qh[mt][kt][2], qh[mt][kt][3], h2, h3);
                    mma_bf16(sacc[mt][2 * ng + 1], qh[mt][kt][0], qh[mt][kt][1], qh[mt][kt][2], qh[mt][kt][3], l2, l3);
                    mma_bf16(sacc[mt][2 * ng + 1], ql[mt][kt][0], ql[mt][kt][1], ql[mt][kt][2], ql[mt][kt][3], h2, h3);
                }
            }
        }

        uint32_t ph[2][4][4], pl[2][4][4];
#pragma unroll
        for (int mt = 0; mt < 2; mt++) {
            float m0 = -1e30f, m1 = -1e30f;
#pragma unroll
            for (int nt = 0; nt < 8; nt++) {
                m0 = fmaxf(m0, fmaxf(sacc[mt][nt].x, sacc[mt][nt].y));
                m1 = fmaxf(m1, fmaxf(sacc[mt][nt].z, sacc[mt][nt].w));
            }
#pragma unroll
            for (int o = 1; o <= 2; o <<= 1) {
                m0 = fmaxf(m0, __shfl_xor_sync(0xffffffffu, m0, o));
                m1 = fmaxf(m1, __shfl_xor_sync(0xffffffffu, m1, o));
            }
            float mn0 = fmaxf(mi[mt][0], m0), mn1 = fmaxf(mi[mt][1], m1);
            float corr0 = exp2f(mi[mt][0] - mn0), corr1 = exp2f(mi[mt][1] - mn1);
            float rs0 = 0.f, rs1 = 0.f;
#pragma unroll
            for (int nt = 0; nt < 8; nt++) {
                sacc[mt][nt].x = exp2f(sacc[mt][nt].x - mn0);
                sacc[mt][nt].y = exp2f(sacc[mt][nt].y - mn0);
                sacc[mt][nt].z = exp2f(sacc[mt][nt].z - mn1);
                sacc[mt][nt].w = exp2f(sacc[mt][nt].w - mn1);
                rs0 += sacc[mt][nt].x + sacc[mt][nt].y;
                rs1 += sacc[mt][nt].z + sacc[mt][nt].w;
            }
#pragma unroll
            for (int o = 1; o <= 2; o <<= 1) {
                rs0 += __shfl_xor_sync(0xffffffffu, rs0, o);
                rs1 += __shfl_xor_sync(0xffffffffu, rs1, o);
            }
            li[mt][0] = li[mt][0] * corr0 + rs0;
            li[mt][1] = li[mt][1] * corr1 + rs1;
            mi[mt][0] = mn0; mi[mt][1] = mn1;
#pragma unroll
            for (int j = 0; j < 8; j++) {
                oacc[mt][j].x *= corr0; oacc[mt][j].y *= corr0;
                oacc[mt][j].z *= corr1; oacc[mt][j].w *= corr1;
            }
#pragma unroll
            for (int t = 0; t < 4; t++) {
                split2(sacc[mt][2 * t].x,     sacc[mt][2 * t].y,     ph[mt][t][0], pl[mt][t][0]);
                split2(sacc[mt][2 * t].z,     sacc[mt][2 * t].w,     ph[mt][t][1], pl[mt][t][1]);
                split2(sacc[mt][2 * t + 1].x, sacc[mt][2 * t + 1].y, ph[mt][t][2], pl[mt][t][2]);
                split2(sacc[mt][2 * t + 1].z, sacc[mt][2 * t + 1].w, ph[mt][t][3], pl[mt][t][3]);
            }
        }

#pragma unroll
        for (int jg = 0; jg < 4; jg++) {
#pragma unroll
            for (int kt = 0; kt < 4; kt++) {
                uint32_t o = laddr + (uint32_t)(jg * 576 + kt * 8) * 4;
                uint32_t h0, h1, h2, h3, l0, l1, l2, l3;
                ldsm_x4(h0, h1, h2, h3, vh_b + o);
                ldsm_x4(l0, l1, l2, l3, vl_b + o);
#pragma unroll
                for (int mt = 0; mt < 2; mt++) {
                    mma_bf16(oacc[mt][2 * jg],     ph[mt][kt][0], ph[mt][kt][1], ph[mt][kt][2], ph[mt][kt][3], h0, h1);
                    mma_bf16(oacc[mt][2 * jg],     ph[mt][kt][0], ph[mt][kt][1], ph[mt][kt][2], ph[mt][kt][3], l0, l1);
                    mma_bf16(oacc[mt][2 * jg],     pl[mt][kt][0], pl[mt][kt][1], pl[mt][kt][2], pl[mt][kt][3], h0, h1);
                    mma_bf16(oacc[mt][2 * jg + 1], ph[mt][kt][0], ph[mt][kt][1], ph[mt][kt][2], ph[mt][kt][3], h2, h3);
                    mma_bf16(oacc[mt][2 * jg + 1], ph[mt][kt][0], ph[mt][kt][1], ph[mt][kt][2], ph[mt][kt][3], l2, l3);
                    mma_bf16(oacc[mt][2 * jg + 1], pl[mt][kt][0], pl[mt][kt][1], pl[mt][kt][2], pl[mt][kt][3], h2, h3);
                }
            }
        }
        __syncthreads();
    }

#pragma unroll
    for (int mt = 0; mt < 2; mt++) {
        float inv0 = 1.f / li[mt][0], inv1 = 1.f / li[mt][1];
        const size_t row0 = ((size_t)b * S_ + q0 + mt * 16 + r) * 512;
        const size_t row1 = row0 + 8 * 512;
#pragma unroll
        for (int j = 0; j < 8; j++) {
            int w = h * 32 + j * 4 + c;
            uint32_t hw, lw;
            split2(oacc[mt][j].x * inv0, oacc[mt][j].y * inv0, hw, lw);
            AOh[row0 + w] = hw; AOl[row0 + w] = lw;
            split2(oacc[mt][j].z * inv1, oacc[mt][j].w * inv1, hw, lw);
            AOh[row1 + w] = hw; AOl[row1 + w] = lw;
        }
    }
}

// ---------------------------------------------------------------------------
extern "C" void kernel_launch(void* const* d_in, const int* in_sizes, int n_in,
                              void* d_out, int out_size)
{
    const float* queries = (const float*)d_in[0];
    const float* keys    = (const float*)d_in[1];
    const float* values  = (const float*)d_in[2];
    const float* W_q = (const float*)d_in[3];
    const float* b_q = (const float*)d_in[4];
    const float* W_k = (const float*)d_in[5];
    const float* b_k = (const float*)d_in[6];
    const float* W_v = (const float*)d_in[7];
    const float* b_v = (const float*)d_in[8];
    const float* W_o = (const float*)d_in[9];
    const float* b_o = (const float*)d_in[10];
    float* out = (float*)d_out;

    uint32_t *Qh, *Ql, *Kh, *Kl, *Vh, *Vl, *AOh, *AOl;
    cudaGetSymbolAddress((void**)&Qh, g_Qh);
    cudaGetSymbolAddress((void**)&Ql, g_Ql);
    cudaGetSymbolAddress((void**)&Kh, g_Kh);
    cudaGetSymbolAddress((void**)&Kl, g_Kl);
    cudaGetSymbolAddress((void**)&Vh, g_Vh);
    cudaGetSymbolAddress((void**)&Vl, g_Vl);
    cudaGetSymbolAddress((void**)&AOh, g_AOh);
    cudaGetSymbolAddress((void**)&AOl, g_AOl);

    const int gsmem = 2 * GSTG * 4;   // 81920
    cudaFuncSetAttribute(gemm_qkv, cudaFuncAttributeMaxDynamicSharedMemorySize, gsmem);
    cudaFuncSetAttribute(gemm_out, cudaFuncAttributeMaxDynamicSharedMemorySize, gsmem);
    const int asmem = 2 * 4 * 64 * 36 * 4;  // 73728
    cudaFuncSetAttribute(attn_mma, cudaFuncAttributeMaxDynamicSharedMemorySize, asmem);

    // 1) split everything
    split_all<<<16384, 256>>>(queries, keys, values, W_q, W_k, W_v, W_o);

    // 2) Q/K/V projections in one launch
    dim3 qkv_grid(D_ / 128, (B_ * S_) / 128, 3);   // (8, 32, 3)
    gemm_qkv<<<qkv_grid, 256, gsmem>>>(b_q, b_k, b_v);

    // 3) attention
    dim3 agrid(S_ / 128, H_, B_);
    attn_mma<<<agrid, 128, asmem>>>(Qh, Ql, Kh, Kl, Vh, Vl, AOh, AOl);

    // 4) O projection
    dim3 ogrid(D_ / 128, (B_ * S_) / 128);
    gemm_out<<<ogrid, 256, gsmem>>>(b_o, out);
}